// round 14
// baseline (speedup 1.0000x reference)
#include <cuda_runtime.h>
#include <math.h>

#define Bsz 2
#define Npts 4096
#define Mpts 4096
#define KK 32
#define CC 64
#define R2 0.0064f

// ---------------- device scratch (no allocs allowed) ----------------
__device__ float g_F[Bsz * Mpts * 128];      // F[b][m][o] = W1[:, :64]·feat[b,:,m] + b1
__device__ int   g_idx[Bsz * Npts * KK];     // ball query indices (compacted)
__device__ int   g_cnt[Bsz * Npts];          // neighbor counts
__device__ float g_rowpart[128];             // per-block partial sums: min over m
__device__ float g_colpart[128];             // per-block partial sums: min over n
__device__ unsigned int g_counter;           // work queue for mlp kernel

// ---------------- packed f32x2 helpers ----------------
__device__ __forceinline__ unsigned long long packdup(float a) {
    unsigned long long r;
    asm("mov.b64 %0, {%1, %1};" : "=l"(r) : "f"(a));
    return r;
}
__device__ __forceinline__ unsigned long long pack2(float a, float b) {
    unsigned long long r;
    asm("mov.b64 %0, {%1, %2};" : "=l"(r) : "f"(a), "f"(b));
    return r;
}
__device__ __forceinline__ void unpack2(unsigned long long v, float& a, float& b) {
    asm("mov.b64 {%0, %1}, %2;" : "=f"(a), "=f"(b) : "l"(v));
}
__device__ __forceinline__ void fma2(unsigned long long& d, unsigned long long a,
                                     unsigned long long b) {
    asm("fma.rn.f32x2 %0, %1, %2, %0;" : "+l"(d) : "l"(a), "l"(b));
}

// ---------------- fused distance scan + F precompute (512-thread blocks) ----
// blocks [0,128): dist row task (64 pts x 8 sub-scans)
// blocks [128,256): dist col task
// blocks [256,272): F GEMM blocks (each: 512 m-values x all 128 outputs)
#define DIST_SMEM (4104 * 16 + 64 * 8 * 32 * 2 + 64 * 4)
__global__ void __launch_bounds__(512, 2) distf_kernel(
    const float* __restrict__ points, const float* __restrict__ knnpoints,
    const float* __restrict__ feat, const float* __restrict__ w1,
    const float* __restrict__ b1)
{
    extern __shared__ __align__(16) unsigned char smem_raw[];
    int t = threadIdx.x;

    if (blockIdx.x >= 256) {
        // ================= F precompute path =================
        float* sw = (float*)smem_raw;     // 8192 floats
        float* sb = sw + 8192;            // 128 floats
        int fbid = blockIdx.x - 256;      // 0..15
        if (fbid == 0 && t == 0) g_counter = 0u;
        for (int e = t; e < 8192; e += 512) {
            int o = e >> 6, c = e & 63;
            sw[(c * 8 + (o >> 4)) * 16 + (o & 15)] = w1[o * 68 + c];
        }
        if (t < 128) sb[t] = b1[t];
        __syncthreads();

        int w    = t >> 5;                // 0..15
        int lane = t & 31;
        int og   = w & 7;
        int mhalf = w >> 3;               // 0 or 1
        const unsigned long long* sbv = (const unsigned long long*)(sb + og * 16);
        int idx_base = fbid * 512;
        int b     = idx_base >> 12;
        int mbase = idx_base & 4095;
        const float* fb = feat + ((size_t)b * 64) * 4096;

#pragma unroll
        for (int it = 0; it < 2; it++) {
            int mloc = mhalf * 256 + it * 128 + lane * 4;
            unsigned long long acc[4][8];
#pragma unroll
            for (int mi = 0; mi < 4; mi++)
#pragma unroll
                for (int k = 0; k < 8; k++) acc[mi][k] = sbv[k];

            const float* fp = fb + mbase + mloc;
#pragma unroll 8
            for (int c = 0; c < 64; c++) {
                float4 f4 = *(const float4*)(fp + c * 4096);
                const unsigned long long* wv =
                    (const unsigned long long*)(sw + (c * 8 + og) * 16);
                unsigned long long x0 = packdup(f4.x), x1 = packdup(f4.y);
                unsigned long long x2 = packdup(f4.z), x3 = packdup(f4.w);
#pragma unroll
                for (int k = 0; k < 8; k++) {
                    unsigned long long wq = wv[k];
                    fma2(acc[0][k], wq, x0);
                    fma2(acc[1][k], wq, x1);
                    fma2(acc[2][k], wq, x2);
                    fma2(acc[3][k], wq, x3);
                }
            }
#pragma unroll
            for (int mi = 0; mi < 4; mi++) {
                float4* dst = (float4*)(g_F + ((size_t)(idx_base + mloc + mi)) * 128 + og * 16);
#pragma unroll
                for (int k = 0; k < 4; k++) {
                    float a0, a1, a2, a3;
                    unpack2(acc[mi][2 * k], a0, a1);
                    unpack2(acc[mi][2 * k + 1], a2, a3);
                    dst[k] = make_float4(a0, a1, a2, a3);
                }
            }
        }
        return;
    }

    // ================= distance path (8 sub-scans per point) ==============
    float4*         sh  = (float4*)smem_raw;                 // 4104 entries (staggered)
    unsigned short* buf = (unsigned short*)(sh + 4104);      // [64][8][32] u16 hits
    float*          red = (float*)(buf + 64 * 8 * 32);       // 64-float reduction

    bool row = blockIdx.x < 128;
    int  ib  = row ? blockIdx.x : blockIdx.x - 128;
    int  pp  = t >> 3;                // point slot 0..63
    int  q   = t & 7;                 // sub-scan 0..7
    int  i   = ib * 64 + pp;
    int  b   = i >> 12;
    int  x   = i & 4095;

    const float* scan = row ? knnpoints : points;
    for (int m = t; m < 4096; m += 512) {
        float qx = scan[(b * 3 + 0) * 4096 + m];
        float qy = scan[(b * 3 + 1) * 4096 + m];
        float qz = scan[(b * 3 + 2) * 4096 + m];
        sh[m + (m >> 9)] = make_float4(qx, qy, qz, fmaf(qx, qx, fmaf(qy, qy, qz * qz)));
    }
    __syncthreads();

    const float* own = row ? points : knnpoints;
    float px = own[(b * 3 + 0) * 4096 + x];
    float py = own[(b * 3 + 1) * 4096 + x];
    float pz = own[(b * 3 + 2) * 4096 + x];
    float pe = fmaf(px, px, fmaf(py, py, pz * pz));

    float minv = 3.402823e38f;
    int   c    = 0;
    unsigned short* mybuf = buf + (pp * 8 + q) * 32;

    int mlo = q * 512, mhi = mlo + 512;
    for (int m0 = mlo; m0 < mhi; m0 += 4) {
        float d2v[4];
#pragma unroll
        for (int u = 0; u < 4; u++) {
            float4 qq = sh[m0 + u + q];
            float dot = fmaf(px, qq.x, fmaf(py, qq.y, pz * qq.z));
            d2v[u] = fmaxf(fmaf(-2.0f, dot, pe + qq.w), 0.0f);
        }
        minv = fminf(minv, fminf(fminf(d2v[0], d2v[1]), fminf(d2v[2], d2v[3])));
        if (row) {
            bool p0 = d2v[0] < R2, p1 = d2v[1] < R2, p2 = d2v[2] < R2, p3 = d2v[3] < R2;
            if (p0 | p1 | p2 | p3) {
                if (p0 && c < KK) { mybuf[c] = (unsigned short)(m0 + 0); c++; }
                if (p1 && c < KK) { mybuf[c] = (unsigned short)(m0 + 1); c++; }
                if (p2 && c < KK) { mybuf[c] = (unsigned short)(m0 + 2); c++; }
                if (p3 && c < KK) { mybuf[c] = (unsigned short)(m0 + 3); c++; }
            }
        }
    }

    // merge min over the 8 sub-scans (lane groups of 8 are warp-aligned)
    minv = fminf(minv, __shfl_xor_sync(0xffffffffu, minv, 1));
    minv = fminf(minv, __shfl_xor_sync(0xffffffffu, minv, 2));
    minv = fminf(minv, __shfl_xor_sync(0xffffffffu, minv, 4));

    if (row) {
        int lane = t & 31, g0 = lane & ~7;
        int pre = 0, tot = 0;
#pragma unroll
        for (int k = 0; k < 8; k++) {
            int ck = __shfl_sync(0xffffffffu, c, g0 + k);
            tot += ck;
            if (k < q) pre += ck;
        }
        int base = i * KK;
        for (int ii = 0; ii < c; ii++) {
            int pos = pre + ii;
            if (pos < KK) g_idx[base + pos] = (int)mybuf[ii];
        }
        if (q == 0) {
            int cnt = tot < KK ? tot : KK;
            g_cnt[i] = cnt;
            if (cnt == 0) g_idx[base] = 0;
        }
    }
    if (q == 0) red[pp] = sqrtf(1e-6f + minv);
    __syncthreads();
    if (t < 32) {
        float s = red[t] + red[t + 32];
#pragma unroll
        for (int off = 16; off > 0; off >>= 1) s += __shfl_xor_sync(0xffffffffu, s, off);
        if (t == 0) {
            if (row) g_rowpart[ib] = s;
            else     g_colpart[ib] = s;
        }
    }
}

// ---------------- dense column-stream MLP (21 warps, low-reg) ----------------
// Shared layout (floats):
//   [0,8192)      W2 packed float4 per (c2, lane)
//   [8192,12288)  W3 packed
//   [12288,12352) b2   [12352,12416) b3
//   [12416,13440) WD1 table: u64[ch][oo][lane]
//   [13440, ...)  per-warp regions, 1600 floats
#define NWARP 21
#define NTHR  672
#define OFF_W2 0
#define OFF_W3 8192
#define OFF_B2 12288
#define OFF_B3 12352
#define OFF_WD1 12416
#define OFF_WARP 13440
#define OFF_H1 64
#define OFF_H2 1088
#define WARP_STRIDE 1600
#define SMEM_FLOATS (OFF_WARP + NWARP * WARP_STRIDE)

__global__ void __launch_bounds__(NTHR, 1) mlp_kernel(
    const float* __restrict__ points, const float* __restrict__ knnpoints,
    const float* __restrict__ w1,
    const float* __restrict__ w2, const float* __restrict__ b2,
    const float* __restrict__ w3, const float* __restrict__ b3,
    float* __restrict__ out)
{
    extern __shared__ __align__(16) unsigned char smem_raw2[];
    float* sm = (float*)smem_raw2;
    int tid = threadIdx.x;

    // W2 packed
    for (int e = tid; e < 64 * 128; e += NTHR) {
        int c2 = e >> 7, z = e & 127, l = z >> 2, s = z & 3;
        int c = 2 * c2 + (s >> 1), o = 2 * l + (s & 1);
        sm[OFF_W2 + e] = w2[o * 128 + c];
    }
    // W3 packed
    for (int e = tid; e < 64 * 64; e += NTHR) {
        int c2 = e >> 7, z = e & 127, l = z >> 2, s = z & 3;
        int c = 2 * c2 + (s >> 1), o = 2 * l + (s & 1);
        sm[OFF_W3 + e] = w3[o * 64 + c];
    }
    if (tid < 64) sm[OFF_B2 + tid] = b2[tid];
    if (tid < 64) sm[OFF_B3 + tid] = b3[tid];
    // WD1 table: u64[ch*128 + oo*32 + l]
    {
        unsigned long long* wd1t = (unsigned long long*)(sm + OFF_WD1);
        for (int e = tid; e < 512; e += NTHR) {
            int ch = e >> 7, r = e & 127, oo = r >> 5, l = r & 31;
            wd1t[e] = packdup(w1[(4 * l + oo) * 68 + 64 + ch]);
        }
    }
    __syncthreads();

    int lane = tid & 31;
    int wrp  = tid >> 5;
    float* ws  = sm + OFF_WARP + wrp * WARP_STRIDE;
    float* h1p = ws + OFF_H1;
    float* h2p = ws + OFF_H2;
    int*   smm  = (int*)ws;
    int*   smi  = (int*)(ws + 8);
    float* smw  = ws + 16;
    int*   smnp = (int*)(ws + 24);
    const float4* w2q = (const float4*)(sm + OFF_W2);
    const float4* w3q = (const float4*)(sm + OFF_W3);
    const unsigned long long* wd1t = (const unsigned long long*)(sm + OFF_WD1);

    float bb2_0 = sm[OFF_B2 + 2 * lane], bb2_1 = sm[OFF_B2 + 2 * lane + 1];
    float bb3_0 = sm[OFF_B3 + 2 * lane], bb3_1 = sm[OFF_B3 + 2 * lane + 1];

    // stream state (warp-uniform)
    int cur_i = 0, cur_cols = 0, cur_j = 0;
    int open_i = -1;
    float agg0 = 0.f, agg1 = 0.f;

    for (;;) {
        // ---- fill up to 8 slots from the column stream ----
        int nslots = 0;
        while (nslots < 8) {
            if (cur_j >= cur_cols) {
                int ni = 0;
                if (lane == 0) ni = (int)atomicAdd(&g_counter, 1u);
                ni = __shfl_sync(0xffffffffu, ni, 0);
                if (ni >= Bsz * Npts) { cur_cols = 0; cur_j = 0; break; }
                cur_i = ni;
                int cc = g_cnt[ni];
                cur_cols = cc > 0 ? cc : 1;
                cur_j = 0;
            }
            int take = cur_cols - cur_j;
            if (take > 8 - nslots) take = 8 - nslots;
            if (lane < take) {
                int slot = nslots + lane;
                int j = cur_j + lane;
                int m = g_idx[cur_i * KK + j];
                int b = cur_i >> 12, n = cur_i & 4095;
                smm[slot] = m;
                smi[slot] = cur_i;
                smw[slot] = (j == 0) ? (float)(KK - cur_cols + 1) : 1.0f;
                smnp[slot] = (j == 0) ? 1 : 0;
                float ppx = points[(b * 3 + 0) * 4096 + n];
                float ppy = points[(b * 3 + 1) * 4096 + n];
                float ppz = points[(b * 3 + 2) * 4096 + n];
                float qx = knnpoints[(b * 3 + 0) * 4096 + m];
                float qy = knnpoints[(b * 3 + 1) * 4096 + m];
                float qz = knnpoints[(b * 3 + 2) * 4096 + m];
                float dx = qx - ppx, dy = qy - ppy, dz = qz - ppz;
                float dd = fmaf(dx, dx, fmaf(dy, dy, dz * dz));
                ws[32 + 0 * 8 + slot] = dx;
                ws[32 + 1 * 8 + slot] = dy;
                ws[32 + 2 * 8 + slot] = dz;
                ws[32 + 3 * 8 + slot] = dd;
            }
            nslots += take;
            cur_j += take;
        }
        __syncwarp();
        if (nslots == 0) break;
        if (nslots < 8) {
            // pad with zero-weight copies of the last real slot (finite operands)
            if (lane >= nslots && lane < 8) {
                int src = nslots - 1;
                smm[lane] = smm[src];
                smi[lane] = smi[src];
                smw[lane] = 0.0f;
                smnp[lane] = 0;
                ws[32 + 0 * 8 + lane] = ws[32 + 0 * 8 + src];
                ws[32 + 1 * 8 + lane] = ws[32 + 1 * 8 + src];
                ws[32 + 2 * 8 + lane] = ws[32 + 2 * 8 + src];
                ws[32 + 3 * 8 + lane] = ws[32 + 3 * 8 + src];
            }
            __syncwarp();
        }

        // ---- layer 1: F[m] + W1d·diff (4 channels), o = 4lane..+3 ----
        {
            float4 Fv[8];
#pragma unroll
            for (int j = 0; j < 8; j++) {
                int m = smm[j];
                int bidx = smi[j] >> 12;
                Fv[j] = *(const float4*)(g_F + ((size_t)((bidx << 12) + m)) * 128 + 4 * lane);
            }
            unsigned long long xch[4][4];
#pragma unroll
            for (int ch = 0; ch < 4; ch++)
#pragma unroll
                for (int jp = 0; jp < 4; jp++)
                    xch[ch][jp] = *(const unsigned long long*)(ws + 32 + ch * 8 + 2 * jp);

            unsigned long long acc[4][4];
#pragma unroll
            for (int jp = 0; jp < 4; jp++) {
                acc[jp][0] = pack2(Fv[2 * jp].x, Fv[2 * jp + 1].x);
                acc[jp][1] = pack2(Fv[2 * jp].y, Fv[2 * jp + 1].y);
                acc[jp][2] = pack2(Fv[2 * jp].z, Fv[2 * jp + 1].z);
                acc[jp][3] = pack2(Fv[2 * jp].w, Fv[2 * jp + 1].w);
            }
#pragma unroll
            for (int ch = 0; ch < 4; ch++) {
                unsigned long long w0 = wd1t[ch * 128 + 0  + lane];
                unsigned long long w1r = wd1t[ch * 128 + 32 + lane];
                unsigned long long w2r = wd1t[ch * 128 + 64 + lane];
                unsigned long long w3r = wd1t[ch * 128 + 96 + lane];
#pragma unroll
                for (int jp = 0; jp < 4; jp++) {
                    fma2(acc[jp][0], w0,  xch[ch][jp]);
                    fma2(acc[jp][1], w1r, xch[ch][jp]);
                    fma2(acc[jp][2], w2r, xch[ch][jp]);
                    fma2(acc[jp][3], w3r, xch[ch][jp]);
                }
            }

            int u0 = 2 * lane, u1 = 2 * lane + 1;
            int p0 = u0 ^ ((u0 >> 3) & 7);
            int p1 = u1 ^ ((u1 >> 3) & 7);
#pragma unroll
            for (int jp = 0; jp < 4; jp++) {
                float v0, v1, v2, v3;
                unpack2(acc[jp][0], v0, v1);
                unpack2(acc[jp][1], v2, v3);
                *(float4*)(h1p + jp * 256 + p0 * 4) =
                    make_float4(fmaxf(v0, 0.f), fmaxf(v1, 0.f), fmaxf(v2, 0.f), fmaxf(v3, 0.f));
                unpack2(acc[jp][2], v0, v1);
                unpack2(acc[jp][3], v2, v3);
                *(float4*)(h1p + jp * 256 + p1 * 4) =
                    make_float4(fmaxf(v0, 0.f), fmaxf(v1, 0.f), fmaxf(v2, 0.f), fmaxf(v3, 0.f));
            }
        }
        __syncwarp();
        // ---- layer 2: 128 -> 64, lane owns o = 2lane, 2lane+1 ----
        {
            unsigned long long acc[4][2];
#pragma unroll
            for (int jp = 0; jp < 4; jp++) {
                acc[jp][0] = packdup(bb2_0);
                acc[jp][1] = packdup(bb2_1);
            }
#pragma unroll
            for (int c4 = 0; c4 < 32; c4++) {
                float4 WA = w2q[(2 * c4) * 32 + lane];
                float4 WB = w2q[(2 * c4 + 1) * 32 + lane];
                unsigned long long wd[4][2];
                wd[0][0] = packdup(WA.x); wd[0][1] = packdup(WA.y);
                wd[1][0] = packdup(WA.z); wd[1][1] = packdup(WA.w);
                wd[2][0] = packdup(WB.x); wd[2][1] = packdup(WB.y);
                wd[3][0] = packdup(WB.z); wd[3][1] = packdup(WB.w);
                int ua = 2 * c4, ub = 2 * c4 + 1;
                int pa = ua ^ ((ua >> 3) & 7);
                int pb = ub ^ ((ub >> 3) & 7);
#pragma unroll
                for (int jp = 0; jp < 4; jp++) {
                    ulonglong2 XA = *(const ulonglong2*)(h1p + jp * 256 + pa * 4);
                    ulonglong2 XB = *(const ulonglong2*)(h1p + jp * 256 + pb * 4);
                    fma2(acc[jp][0], wd[0][0], XA.x); fma2(acc[jp][1], wd[0][1], XA.x);
                    fma2(acc[jp][0], wd[1][0], XA.y); fma2(acc[jp][1], wd[1][1], XA.y);
                    fma2(acc[jp][0], wd[2][0], XB.x); fma2(acc[jp][1], wd[2][1], XB.x);
                    fma2(acc[jp][0], wd[3][0], XB.y); fma2(acc[jp][1], wd[3][1], XB.y);
                }
            }
#pragma unroll
            for (int jp = 0; jp < 4; jp++) {
                float v0, v1, v2, v3;
                unpack2(acc[jp][0], v0, v1);
                unpack2(acc[jp][1], v2, v3);
                *(float4*)(h2p + jp * 128 + 4 * lane) =
                    make_float4(fmaxf(v0, 0.f), fmaxf(v1, 0.f), fmaxf(v2, 0.f), fmaxf(v3, 0.f));
            }
        }
        __syncwarp();
        // ---- layer 3: 64 -> 64 + streaming aggregate with point flush ----
        {
            unsigned long long acc[4][2];
#pragma unroll
            for (int jp = 0; jp < 4; jp++) {
                acc[jp][0] = packdup(bb3_0);
                acc[jp][1] = packdup(bb3_1);
            }
#pragma unroll
            for (int c4 = 0; c4 < 16; c4++) {
                float4 WA = w3q[(2 * c4) * 32 + lane];
                float4 WB = w3q[(2 * c4 + 1) * 32 + lane];
                unsigned long long wd[4][2];
                wd[0][0] = packdup(WA.x); wd[0][1] = packdup(WA.y);
                wd[1][0] = packdup(WA.z); wd[1][1] = packdup(WA.w);
                wd[2][0] = packdup(WB.x); wd[2][1] = packdup(WB.y);
                wd[3][0] = packdup(WB.z); wd[3][1] = packdup(WB.w);
#pragma unroll
                for (int jp = 0; jp < 4; jp++) {
                    ulonglong2 XA = *(const ulonglong2*)(h2p + jp * 128 + 8 * c4);
                    ulonglong2 XB = *(const ulonglong2*)(h2p + jp * 128 + 8 * c4 + 4);
                    fma2(acc[jp][0], wd[0][0], XA.x); fma2(acc[jp][1], wd[0][1], XA.x);
                    fma2(acc[jp][0], wd[1][0], XA.y); fma2(acc[jp][1], wd[1][1], XA.y);
                    fma2(acc[jp][0], wd[2][0], XB.x); fma2(acc[jp][1], wd[2][1], XB.x);
                    fma2(acc[jp][0], wd[3][0], XB.y); fma2(acc[jp][1], wd[3][1], XB.y);
                }
            }
#pragma unroll
            for (int jp = 0; jp < 4; jp++) {
                float v00, v01, v10, v11;
                unpack2(acc[jp][0], v00, v01);
                unpack2(acc[jp][1], v10, v11);
#pragma unroll
                for (int h = 0; h < 2; h++) {
                    int col = 2 * jp + h;
                    float va = h ? v01 : v00;
                    float vb = h ? v11 : v10;
                    if (smnp[col]) {
                        if (open_i >= 0) {
                            int fb = open_i >> 12, fn = open_i & 4095;
                            out[((size_t)(fb * 64 + 2 * lane + 0)) * 4096 + fn] = agg0;
                            out[((size_t)(fb * 64 + 2 * lane + 1)) * 4096 + fn] = agg1;
                        }
                        open_i = smi[col];
                        agg0 = 0.f; agg1 = 0.f;
                    }
                    float w = smw[col];
                    agg0 = fmaf(w, fmaxf(va, 0.f), agg0);
                    agg1 = fmaf(w, fmaxf(vb, 0.f), agg1);
                }
            }
        }
        __syncwarp();
    }

    // flush the last open point
    if (open_i >= 0) {
        int fb = open_i >> 12, fn = open_i & 4095;
        out[((size_t)(fb * 64 + 2 * lane + 0)) * 4096 + fn] = agg0;
        out[((size_t)(fb * 64 + 2 * lane + 1)) * 4096 + fn] = agg1;
    }

    // ---- folded loss reduction (depends only on dist results) ----
    if (blockIdx.x == 0 && tid < 32) {
        float s = 0.f;
        for (int t = tid; t < 128; t += 32) s += g_rowpart[t] + g_colpart[t];
#pragma unroll
        for (int off = 16; off > 0; off >>= 1) s += __shfl_xor_sync(0xffffffffu, s, off);
        if (tid == 0) out[Bsz * 64 * Npts] = s * (1.0f / 8192.0f);
    }
}

extern "C" void kernel_launch(void* const* d_in, const int* in_sizes, int n_in,
                              void* d_out, int out_size) {
    const float* points    = (const float*)d_in[0];
    const float* knnpoints = (const float*)d_in[1];
    const float* feat      = (const float*)d_in[2];
    const float* w1 = (const float*)d_in[3];
    const float* b1 = (const float*)d_in[4];
    const float* w2 = (const float*)d_in[5];
    const float* b2 = (const float*)d_in[6];
    const float* w3 = (const float*)d_in[7];
    const float* b3 = (const float*)d_in[8];
    float* out = (float*)d_out;

    cudaFuncSetAttribute(distf_kernel, cudaFuncAttributeMaxDynamicSharedMemorySize, DIST_SMEM);
    cudaFuncSetAttribute(mlp_kernel,   cudaFuncAttributeMaxDynamicSharedMemorySize, SMEM_FLOATS * 4);

    int nsm = 148;
    cudaDeviceGetAttribute(&nsm, cudaDevAttrMultiProcessorCount, 0);

    distf_kernel<<<272, 512, DIST_SMEM>>>(points, knnpoints, feat, w1, b1);
    mlp_kernel<<<nsm, NTHR, SMEM_FLOATS * 4>>>(points, knnpoints, w1, w2, b2, w3, b3, out);
}

// round 15
// speedup vs baseline: 2.3942x; 2.3942x over previous
#include <cuda_runtime.h>
#include <math.h>

#define Bsz 2
#define Npts 4096
#define Mpts 4096
#define KK 32
#define CC 64
#define R2 0.0064f

// ---------------- device scratch (no allocs allowed) ----------------
__device__ float g_F[Bsz * Mpts * 128];      // F[b][m][o] = W1[:, :64]·feat[b,:,m] + b1
__device__ int   g_idx[Bsz * Npts * KK];     // ball query indices (compacted)
__device__ int   g_cnt[Bsz * Npts];          // neighbor counts
__device__ float g_rowpart[256];             // per-block partial sums: min over m
__device__ float g_colpart[256];             // per-block partial sums: min over n
__device__ unsigned int g_counter;           // work queue for mlp kernel

// ---------------- packed f32x2 helpers ----------------
__device__ __forceinline__ unsigned long long packdup(float a) {
    unsigned long long r;
    asm("mov.b64 %0, {%1, %1};" : "=l"(r) : "f"(a));
    return r;
}
__device__ __forceinline__ unsigned long long pack2(float a, float b) {
    unsigned long long r;
    asm("mov.b64 %0, {%1, %2};" : "=l"(r) : "f"(a), "f"(b));
    return r;
}
__device__ __forceinline__ void unpack2(unsigned long long v, float& a, float& b) {
    asm("mov.b64 {%0, %1}, %2;" : "=f"(a), "=f"(b) : "l"(v));
}
__device__ __forceinline__ void fma2(unsigned long long& d, unsigned long long a,
                                     unsigned long long b) {
    asm("fma.rn.f32x2 %0, %1, %2, %0;" : "+l"(d) : "l"(a), "l"(b));
}
__device__ __forceinline__ unsigned long long mul2(unsigned long long a,
                                                   unsigned long long b) {
    unsigned long long r;
    asm("mul.rn.f32x2 %0, %1, %2;" : "=l"(r) : "l"(a), "l"(b));
    return r;
}
__device__ __forceinline__ unsigned long long add2(unsigned long long a,
                                                   unsigned long long b) {
    unsigned long long r;
    asm("add.rn.f32x2 %0, %1, %2;" : "=l"(r) : "l"(a), "l"(b));
    return r;
}

// ---------------- fused distance scan + F precompute ----------------
// blocks [0,256): dist row task (32 pts/block, m split over 8 warps, f32x2 packed)
// blocks [256,512): dist col task
// blocks [512,544): F GEMM blocks (256 m-values x all 128 outputs)
// smem: shA 2048 f4 | shB 2048 f4 | buf u16[8][32][32] | cmin[8][32] | ccnt[8][32] | red[32]
#define DIST_SMEM (2048 * 16 * 2 + 8 * 32 * 32 * 2 + 8 * 32 * 4 * 2 + 32 * 4)
__global__ void __launch_bounds__(256, 2) distf_kernel(
    const float* __restrict__ points, const float* __restrict__ knnpoints,
    const float* __restrict__ feat, const float* __restrict__ w1,
    const float* __restrict__ b1)
{
    extern __shared__ __align__(16) unsigned char smem_raw[];
    int t = threadIdx.x;

    if (blockIdx.x >= 512) {
        // ================= F precompute path (R13-proven) =================
        float* sw = (float*)smem_raw;     // 8192 floats
        float* sb = sw + 8192;            // 128 floats
        int fbid = blockIdx.x - 512;      // 0..31
        if (fbid == 0 && t == 0) g_counter = 0u;
        for (int e = t; e < 8192; e += 256) {
            int o = e >> 6, c = e & 63;
            sw[(c * 8 + (o >> 4)) * 16 + (o & 15)] = w1[o * 68 + c];
        }
        if (t < 128) sb[t] = b1[t];
        __syncthreads();

        int og   = t >> 5;
        int lane = t & 31;
        const unsigned long long* sbv = (const unsigned long long*)(sb + og * 16);
        int idx_base = fbid * 256;
        int b     = idx_base >> 12;
        int mbase = idx_base & 4095;
        const float* fb = feat + ((size_t)b * 64) * 4096;

#pragma unroll
        for (int it = 0; it < 2; it++) {
            int mloc = it * 128 + lane * 4;
            unsigned long long acc[4][8];
#pragma unroll
            for (int mi = 0; mi < 4; mi++)
#pragma unroll
                for (int k = 0; k < 8; k++) acc[mi][k] = sbv[k];

            const float* fp = fb + mbase + mloc;
#pragma unroll 8
            for (int c = 0; c < 64; c++) {
                float4 f4 = *(const float4*)(fp + c * 4096);
                const unsigned long long* wv =
                    (const unsigned long long*)(sw + (c * 8 + og) * 16);
                unsigned long long x0 = packdup(f4.x), x1 = packdup(f4.y);
                unsigned long long x2 = packdup(f4.z), x3 = packdup(f4.w);
#pragma unroll
                for (int k = 0; k < 8; k++) {
                    unsigned long long wq = wv[k];
                    fma2(acc[0][k], wq, x0);
                    fma2(acc[1][k], wq, x1);
                    fma2(acc[2][k], wq, x2);
                    fma2(acc[3][k], wq, x3);
                }
            }
#pragma unroll
            for (int mi = 0; mi < 4; mi++) {
                float4* dst = (float4*)(g_F + ((size_t)(idx_base + mloc + mi)) * 128 + og * 16);
#pragma unroll
                for (int k = 0; k < 4; k++) {
                    float a0, a1, a2, a3;
                    unpack2(acc[mi][2 * k], a0, a1);
                    unpack2(acc[mi][2 * k + 1], a2, a3);
                    dst[k] = make_float4(a0, a1, a2, a3);
                }
            }
        }
        return;
    }

    // ================= distance path: broadcast + f32x2 ==================
    float4*         shA  = (float4*)smem_raw;                // 2048 pairs (qx,qy)
    float4*         shB  = shA + 2048;                       // 2048 pairs (qz,qw)
    unsigned short* buf  = (unsigned short*)(shB + 2048);    // [w][lane][32]
    float*          cmin = (float*)(buf + 8 * 32 * 32);      // [w][lane]
    int*            ccnt = (int*)(cmin + 8 * 32);            // [w][lane]
    float*          red  = (float*)(ccnt + 8 * 32);          // [32]

    int  w    = t >> 5;               // warp = m-range 0..7
    int  lane = t & 31;               // lane = point slot 0..31
    bool row  = blockIdx.x < 256;
    int  ib   = row ? blockIdx.x : blockIdx.x - 256;
    int  i    = ib * 32 + lane;       // point index 0..8191 (b uniform per block)
    int  b    = i >> 12;
    int  x    = i & 4095;

    // build packed tile: per pair p -> A={qx0,qx1,qy0,qy1}, B={qz0,qz1,qw0,qw1}
    const float* scan = row ? knnpoints : points;
    for (int p = t; p < 2048; p += 256) {
        int m = 2 * p;
        float2 qx = *(const float2*)(scan + (b * 3 + 0) * 4096 + m);
        float2 qy = *(const float2*)(scan + (b * 3 + 1) * 4096 + m);
        float2 qz = *(const float2*)(scan + (b * 3 + 2) * 4096 + m);
        float w0 = fmaf(qx.x, qx.x, fmaf(qy.x, qy.x, qz.x * qz.x));
        float w1n = fmaf(qx.y, qx.y, fmaf(qy.y, qy.y, qz.y * qz.y));
        shA[p] = make_float4(qx.x, qx.y, qy.x, qy.y);
        shB[p] = make_float4(qz.x, qz.y, w0, w1n);
    }
    __syncthreads();

    const float* own = row ? points : knnpoints;
    float px = own[(b * 3 + 0) * 4096 + x];
    float py = own[(b * 3 + 1) * 4096 + x];
    float pz = own[(b * 3 + 2) * 4096 + x];
    float pe = fmaf(px, px, fmaf(py, py, pz * pz));

    unsigned long long pxd = packdup(px), pyd = packdup(py), pzd = packdup(pz);
    unsigned long long ped = packdup(pe), n2d = packdup(-2.0f);

    float minv = 3.402823e38f;
    int   c    = 0;
    unsigned short* mybuf = buf + (w * 32 + lane) * 32;

    int plo = w * 256, phi = plo + 256;   // 256 pairs = 512 m per warp
    for (int p0 = plo; p0 < phi; p0 += 2) {
#pragma unroll
        for (int u = 0; u < 2; u++) {
            int p = p0 + u;
            ulonglong2 Av = *(const ulonglong2*)(shA + p);  // qx pair, qy pair
            ulonglong2 Bv = *(const ulonglong2*)(shB + p);  // qz pair, qw pair
            // dot = fmaf(px,qx, fmaf(py,qy, pz*qz)) — bitwise same as scalar path
            unsigned long long dot2 = mul2(pzd, Bv.x);
            fma2(dot2, pyd, Av.y);
            fma2(dot2, pxd, Av.x);
            unsigned long long d2p = add2(ped, Bv.y);       // pe + qw
            fma2(d2p, n2d, dot2);                           // + (-2)*dot
            float d0, d1;
            unpack2(d2p, d0, d1);
            float pm = fminf(d0, d1);
            minv = fminf(minv, pm);
            if (row && pm < R2) {                           // rare path
                int m0 = 2 * p;
                if (d0 < R2 && c < KK) { mybuf[c] = (unsigned short)m0; c++; }
                if (d1 < R2 && c < KK) { mybuf[c] = (unsigned short)(m0 + 1); c++; }
            }
        }
    }

    cmin[w * 32 + lane] = minv;
    ccnt[w * 32 + lane] = c;
    __syncthreads();

    if (row) {
        // prefix-merge hits across the 8 m-range warps (ascending m preserved)
        int pre = 0, tot = 0;
#pragma unroll
        for (int k = 0; k < 8; k++) {
            int ck = ccnt[k * 32 + lane];
            tot += ck;
            if (k < w) pre += ck;
        }
        int base = i * KK;
        for (int ii = 0; ii < c; ii++) {
            int pos = pre + ii;
            if (pos < KK) g_idx[base + pos] = (int)mybuf[ii];
        }
        if (w == 0) {
            int cnt = tot < KK ? tot : KK;
            g_cnt[i] = cnt;
            if (cnt == 0) g_idx[base] = 0;
        }
    }
    if (w == 0) {
        float mv = cmin[lane];
#pragma unroll
        for (int k = 1; k < 8; k++) mv = fminf(mv, cmin[k * 32 + lane]);
        mv = fmaxf(mv, 0.0f);   // clamp-before-min == max(rawmin, 0)
        red[lane] = sqrtf(1e-6f + mv);
    }
    __syncthreads();
    if (t < 32) {
        float s = red[t];
#pragma unroll
        for (int off = 16; off > 0; off >>= 1) s += __shfl_xor_sync(0xffffffffu, s, off);
        if (t == 0) {
            if (row) g_rowpart[ib] = s;
            else     g_colpart[ib] = s;
        }
    }
}

// ---------------- dense column-stream MLP (R13-proven: 20 warps) ----------------
#define NWARP 20
#define NTHR  640
#define OFF_W2 0
#define OFF_W3 8192
#define OFF_B2 12288
#define OFF_B3 12352
#define OFF_WD1 12416
#define OFF_WARP 13440
#define OFF_H1 64
#define OFF_H2 1088
#define WARP_STRIDE 1600
#define SMEM_FLOATS (OFF_WARP + NWARP * WARP_STRIDE)

__global__ void __launch_bounds__(NTHR, 1) mlp_kernel(
    const float* __restrict__ points, const float* __restrict__ knnpoints,
    const float* __restrict__ w1,
    const float* __restrict__ w2, const float* __restrict__ b2,
    const float* __restrict__ w3, const float* __restrict__ b3,
    float* __restrict__ out)
{
    extern __shared__ __align__(16) unsigned char smem_raw2[];
    float* sm = (float*)smem_raw2;
    int tid = threadIdx.x;

    // W2 packed
    for (int e = tid; e < 64 * 128; e += NTHR) {
        int c2 = e >> 7, z = e & 127, l = z >> 2, s = z & 3;
        int c = 2 * c2 + (s >> 1), o = 2 * l + (s & 1);
        sm[OFF_W2 + e] = w2[o * 128 + c];
    }
    // W3 packed
    for (int e = tid; e < 64 * 64; e += NTHR) {
        int c2 = e >> 7, z = e & 127, l = z >> 2, s = z & 3;
        int c = 2 * c2 + (s >> 1), o = 2 * l + (s & 1);
        sm[OFF_W3 + e] = w3[o * 64 + c];
    }
    if (tid < 64) sm[OFF_B2 + tid] = b2[tid];
    if (tid < 64) sm[OFF_B3 + tid] = b3[tid];
    // WD1 table: u64[ch*128 + oo*32 + l]
    {
        unsigned long long* wd1t = (unsigned long long*)(sm + OFF_WD1);
        for (int e = tid; e < 512; e += NTHR) {
            int ch = e >> 7, r = e & 127, oo = r >> 5, l = r & 31;
            wd1t[e] = packdup(w1[(4 * l + oo) * 68 + 64 + ch]);
        }
    }
    __syncthreads();

    int lane = tid & 31;
    int wrp  = tid >> 5;
    float* ws  = sm + OFF_WARP + wrp * WARP_STRIDE;
    float* h1p = ws + OFF_H1;
    float* h2p = ws + OFF_H2;
    int*   smm  = (int*)ws;
    int*   smi  = (int*)(ws + 8);
    float* smw  = ws + 16;
    int*   smnp = (int*)(ws + 24);
    const float4* w2q = (const float4*)(sm + OFF_W2);
    const float4* w3q = (const float4*)(sm + OFF_W3);
    const unsigned long long* wd1t = (const unsigned long long*)(sm + OFF_WD1);

    float bb2_0 = sm[OFF_B2 + 2 * lane], bb2_1 = sm[OFF_B2 + 2 * lane + 1];
    float bb3_0 = sm[OFF_B3 + 2 * lane], bb3_1 = sm[OFF_B3 + 2 * lane + 1];

    // stream state (warp-uniform)
    int cur_i = 0, cur_cols = 0, cur_j = 0;
    int open_i = -1;
    float agg0 = 0.f, agg1 = 0.f;

    for (;;) {
        // ---- fill up to 8 slots from the column stream ----
        int nslots = 0;
        while (nslots < 8) {
            if (cur_j >= cur_cols) {
                int ni = 0;
                if (lane == 0) ni = (int)atomicAdd(&g_counter, 1u);
                ni = __shfl_sync(0xffffffffu, ni, 0);
                if (ni >= Bsz * Npts) { cur_cols = 0; cur_j = 0; break; }
                cur_i = ni;
                int cc = g_cnt[ni];
                cur_cols = cc > 0 ? cc : 1;
                cur_j = 0;
            }
            int take = cur_cols - cur_j;
            if (take > 8 - nslots) take = 8 - nslots;
            if (lane < take) {
                int slot = nslots + lane;
                int j = cur_j + lane;
                int m = g_idx[cur_i * KK + j];
                int b = cur_i >> 12, n = cur_i & 4095;
                smm[slot] = m;
                smi[slot] = cur_i;
                smw[slot] = (j == 0) ? (float)(KK - cur_cols + 1) : 1.0f;
                smnp[slot] = (j == 0) ? 1 : 0;
                float ppx = points[(b * 3 + 0) * 4096 + n];
                float ppy = points[(b * 3 + 1) * 4096 + n];
                float ppz = points[(b * 3 + 2) * 4096 + n];
                float qx = knnpoints[(b * 3 + 0) * 4096 + m];
                float qy = knnpoints[(b * 3 + 1) * 4096 + m];
                float qz = knnpoints[(b * 3 + 2) * 4096 + m];
                float dx = qx - ppx, dy = qy - ppy, dz = qz - ppz;
                float dd = fmaf(dx, dx, fmaf(dy, dy, dz * dz));
                ws[32 + 0 * 8 + slot] = dx;
                ws[32 + 1 * 8 + slot] = dy;
                ws[32 + 2 * 8 + slot] = dz;
                ws[32 + 3 * 8 + slot] = dd;
            }
            nslots += take;
            cur_j += take;
        }
        __syncwarp();
        if (nslots == 0) break;
        if (nslots < 8) {
            // pad with zero-weight copies of the last real slot (finite operands)
            if (lane >= nslots && lane < 8) {
                int src = nslots - 1;
                smm[lane] = smm[src];
                smi[lane] = smi[src];
                smw[lane] = 0.0f;
                smnp[lane] = 0;
                ws[32 + 0 * 8 + lane] = ws[32 + 0 * 8 + src];
                ws[32 + 1 * 8 + lane] = ws[32 + 1 * 8 + src];
                ws[32 + 2 * 8 + lane] = ws[32 + 2 * 8 + src];
                ws[32 + 3 * 8 + lane] = ws[32 + 3 * 8 + src];
            }
            __syncwarp();
        }

        // ---- layer 1: F[m] + W1d·diff (4 channels), o = 4lane..+3 ----
        {
            float4 Fv[8];
#pragma unroll
            for (int j = 0; j < 8; j++) {
                int m = smm[j];
                int bidx = smi[j] >> 12;
                Fv[j] = *(const float4*)(g_F + ((size_t)((bidx << 12) + m)) * 128 + 4 * lane);
            }
            unsigned long long xch[4][4];
#pragma unroll
            for (int ch = 0; ch < 4; ch++)
#pragma unroll
                for (int jp = 0; jp < 4; jp++)
                    xch[ch][jp] = *(const unsigned long long*)(ws + 32 + ch * 8 + 2 * jp);

            unsigned long long acc[4][4];
#pragma unroll
            for (int jp = 0; jp < 4; jp++) {
                acc[jp][0] = pack2(Fv[2 * jp].x, Fv[2 * jp + 1].x);
                acc[jp][1] = pack2(Fv[2 * jp].y, Fv[2 * jp + 1].y);
                acc[jp][2] = pack2(Fv[2 * jp].z, Fv[2 * jp + 1].z);
                acc[jp][3] = pack2(Fv[2 * jp].w, Fv[2 * jp + 1].w);
            }
#pragma unroll
            for (int ch = 0; ch < 4; ch++) {
                unsigned long long w0 = wd1t[ch * 128 + 0  + lane];
                unsigned long long w1r = wd1t[ch * 128 + 32 + lane];
                unsigned long long w2r = wd1t[ch * 128 + 64 + lane];
                unsigned long long w3r = wd1t[ch * 128 + 96 + lane];
#pragma unroll
                for (int jp = 0; jp < 4; jp++) {
                    fma2(acc[jp][0], w0,  xch[ch][jp]);
                    fma2(acc[jp][1], w1r, xch[ch][jp]);
                    fma2(acc[jp][2], w2r, xch[ch][jp]);
                    fma2(acc[jp][3], w3r, xch[ch][jp]);
                }
            }

            int u0 = 2 * lane, u1 = 2 * lane + 1;
            int p0 = u0 ^ ((u0 >> 3) & 7);
            int p1 = u1 ^ ((u1 >> 3) & 7);
#pragma unroll
            for (int jp = 0; jp < 4; jp++) {
                float v0, v1, v2, v3;
                unpack2(acc[jp][0], v0, v1);
                unpack2(acc[jp][1], v2, v3);
                *(float4*)(h1p + jp * 256 + p0 * 4) =
                    make_float4(fmaxf(v0, 0.f), fmaxf(v1, 0.f), fmaxf(v2, 0.f), fmaxf(v3, 0.f));
                unpack2(acc[jp][2], v0, v1);
                unpack2(acc[jp][3], v2, v3);
                *(float4*)(h1p + jp * 256 + p1 * 4) =
                    make_float4(fmaxf(v0, 0.f), fmaxf(v1, 0.f), fmaxf(v2, 0.f), fmaxf(v3, 0.f));
            }
        }
        __syncwarp();
        // ---- layer 2: 128 -> 64, lane owns o = 2lane, 2lane+1 ----
        {
            unsigned long long acc[4][2];
#pragma unroll
            for (int jp = 0; jp < 4; jp++) {
                acc[jp][0] = packdup(bb2_0);
                acc[jp][1] = packdup(bb2_1);
            }
#pragma unroll
            for (int c4 = 0; c4 < 32; c4++) {
                float4 WA = w2q[(2 * c4) * 32 + lane];
                float4 WB = w2q[(2 * c4 + 1) * 32 + lane];
                unsigned long long wd[4][2];
                wd[0][0] = packdup(WA.x); wd[0][1] = packdup(WA.y);
                wd[1][0] = packdup(WA.z); wd[1][1] = packdup(WA.w);
                wd[2][0] = packdup(WB.x); wd[2][1] = packdup(WB.y);
                wd[3][0] = packdup(WB.z); wd[3][1] = packdup(WB.w);
                int ua = 2 * c4, ub = 2 * c4 + 1;
                int pa = ua ^ ((ua >> 3) & 7);
                int pb = ub ^ ((ub >> 3) & 7);
#pragma unroll
                for (int jp = 0; jp < 4; jp++) {
                    ulonglong2 XA = *(const ulonglong2*)(h1p + jp * 256 + pa * 4);
                    ulonglong2 XB = *(const ulonglong2*)(h1p + jp * 256 + pb * 4);
                    fma2(acc[jp][0], wd[0][0], XA.x); fma2(acc[jp][1], wd[0][1], XA.x);
                    fma2(acc[jp][0], wd[1][0], XA.y); fma2(acc[jp][1], wd[1][1], XA.y);
                    fma2(acc[jp][0], wd[2][0], XB.x); fma2(acc[jp][1], wd[2][1], XB.x);
                    fma2(acc[jp][0], wd[3][0], XB.y); fma2(acc[jp][1], wd[3][1], XB.y);
                }
            }
#pragma unroll
            for (int jp = 0; jp < 4; jp++) {
                float v0, v1, v2, v3;
                unpack2(acc[jp][0], v0, v1);
                unpack2(acc[jp][1], v2, v3);
                *(float4*)(h2p + jp * 128 + 4 * lane) =
                    make_float4(fmaxf(v0, 0.f), fmaxf(v1, 0.f), fmaxf(v2, 0.f), fmaxf(v3, 0.f));
            }
        }
        __syncwarp();
        // ---- layer 3: 64 -> 64 + streaming aggregate with point flush ----
        {
            unsigned long long acc[4][2];
#pragma unroll
            for (int jp = 0; jp < 4; jp++) {
                acc[jp][0] = packdup(bb3_0);
                acc[jp][1] = packdup(bb3_1);
            }
#pragma unroll
            for (int c4 = 0; c4 < 16; c4++) {
                float4 WA = w3q[(2 * c4) * 32 + lane];
                float4 WB = w3q[(2 * c4 + 1) * 32 + lane];
                unsigned long long wd[4][2];
                wd[0][0] = packdup(WA.x); wd[0][1] = packdup(WA.y);
                wd[1][0] = packdup(WA.z); wd[1][1] = packdup(WA.w);
                wd[2][0] = packdup(WB.x); wd[2][1] = packdup(WB.y);
                wd[3][0] = packdup(WB.z); wd[3][1] = packdup(WB.w);
#pragma unroll
                for (int jp = 0; jp < 4; jp++) {
                    ulonglong2 XA = *(const ulonglong2*)(h2p + jp * 128 + 8 * c4);
                    ulonglong2 XB = *(const ulonglong2*)(h2p + jp * 128 + 8 * c4 + 4);
                    fma2(acc[jp][0], wd[0][0], XA.x); fma2(acc[jp][1], wd[0][1], XA.x);
                    fma2(acc[jp][0], wd[1][0], XA.y); fma2(acc[jp][1], wd[1][1], XA.y);
                    fma2(acc[jp][0], wd[2][0], XB.x); fma2(acc[jp][1], wd[2][1], XB.x);
                    fma2(acc[jp][0], wd[3][0], XB.y); fma2(acc[jp][1], wd[3][1], XB.y);
                }
            }
#pragma unroll
            for (int jp = 0; jp < 4; jp++) {
                float v00, v01, v10, v11;
                unpack2(acc[jp][0], v00, v01);
                unpack2(acc[jp][1], v10, v11);
#pragma unroll
                for (int h = 0; h < 2; h++) {
                    int col = 2 * jp + h;
                    float va = h ? v01 : v00;
                    float vb = h ? v11 : v10;
                    if (smnp[col]) {
                        if (open_i >= 0) {
                            int fb = open_i >> 12, fn = open_i & 4095;
                            out[((size_t)(fb * 64 + 2 * lane + 0)) * 4096 + fn] = agg0;
                            out[((size_t)(fb * 64 + 2 * lane + 1)) * 4096 + fn] = agg1;
                        }
                        open_i = smi[col];
                        agg0 = 0.f; agg1 = 0.f;
                    }
                    float w = smw[col];
                    agg0 = fmaf(w, fmaxf(va, 0.f), agg0);
                    agg1 = fmaf(w, fmaxf(vb, 0.f), agg1);
                }
            }
        }
        __syncwarp();
    }

    // flush the last open point
    if (open_i >= 0) {
        int fb = open_i >> 12, fn = open_i & 4095;
        out[((size_t)(fb * 64 + 2 * lane + 0)) * 4096 + fn] = agg0;
        out[((size_t)(fb * 64 + 2 * lane + 1)) * 4096 + fn] = agg1;
    }

    // ---- folded loss reduction (depends only on dist results) ----
    if (blockIdx.x == 0 && tid < 32) {
        float s = 0.f;
        for (int t2 = tid; t2 < 256; t2 += 32) s += g_rowpart[t2] + g_colpart[t2];
#pragma unroll
        for (int off = 16; off > 0; off >>= 1) s += __shfl_xor_sync(0xffffffffu, s, off);
        if (tid == 0) out[Bsz * 64 * Npts] = s * (1.0f / 8192.0f);
    }
}

extern "C" void kernel_launch(void* const* d_in, const int* in_sizes, int n_in,
                              void* d_out, int out_size) {
    const float* points    = (const float*)d_in[0];
    const float* knnpoints = (const float*)d_in[1];
    const float* feat      = (const float*)d_in[2];
    const float* w1 = (const float*)d_in[3];
    const float* b1 = (const float*)d_in[4];
    const float* w2 = (const float*)d_in[5];
    const float* b2 = (const float*)d_in[6];
    const float* w3 = (const float*)d_in[7];
    const float* b3 = (const float*)d_in[8];
    float* out = (float*)d_out;

    cudaFuncSetAttribute(distf_kernel, cudaFuncAttributeMaxDynamicSharedMemorySize, DIST_SMEM);
    cudaFuncSetAttribute(mlp_kernel,   cudaFuncAttributeMaxDynamicSharedMemorySize, SMEM_FLOATS * 4);

    int nsm = 148;
    cudaDeviceGetAttribute(&nsm, cudaDevAttrMultiProcessorCount, 0);

    distf_kernel<<<544, 256, DIST_SMEM>>>(points, knnpoints, feat, w1, b1);
    mlp_kernel<<<nsm, NTHR, SMEM_FLOATS * 4>>>(points, knnpoints, w1, w2, b2, w3, b3, out);
}

// round 16
// speedup vs baseline: 2.4322x; 1.0159x over previous
#include <cuda_runtime.h>
#include <math.h>

#define Bsz 2
#define Npts 4096
#define Mpts 4096
#define KK 32
#define CC 64
#define R2 0.0064f

// ---------------- device scratch (no allocs allowed) ----------------
__device__ float g_F[Bsz * Mpts * 128];      // F[b][m][o] = W1[:, :64]·feat[b,:,m] + b1
__device__ int   g_idx[Bsz * Npts * KK];     // ball query indices (compacted)
__device__ int   g_cnt[Bsz * Npts];          // neighbor counts
__device__ float g_rowpart[256];             // per-block partial sums: min over m
__device__ float g_colpart[256];             // per-block partial sums: min over n
__device__ unsigned int g_counter;           // work queue for mlp kernel

// ---------------- packed f32x2 helpers ----------------
__device__ __forceinline__ unsigned long long packdup(float a) {
    unsigned long long r;
    asm("mov.b64 %0, {%1, %1};" : "=l"(r) : "f"(a));
    return r;
}
__device__ __forceinline__ unsigned long long pack2(float a, float b) {
    unsigned long long r;
    asm("mov.b64 %0, {%1, %2};" : "=l"(r) : "f"(a), "f"(b));
    return r;
}
__device__ __forceinline__ void unpack2(unsigned long long v, float& a, float& b) {
    asm("mov.b64 {%0, %1}, %2;" : "=f"(a), "=f"(b) : "l"(v));
}
__device__ __forceinline__ void fma2(unsigned long long& d, unsigned long long a,
                                     unsigned long long b) {
    asm("fma.rn.f32x2 %0, %1, %2, %0;" : "+l"(d) : "l"(a), "l"(b));
}
__device__ __forceinline__ unsigned long long mul2(unsigned long long a,
                                                   unsigned long long b) {
    unsigned long long r;
    asm("mul.rn.f32x2 %0, %1, %2;" : "=l"(r) : "l"(a), "l"(b));
    return r;
}
__device__ __forceinline__ unsigned long long add2(unsigned long long a,
                                                   unsigned long long b) {
    unsigned long long r;
    asm("add.rn.f32x2 %0, %1, %2;" : "=l"(r) : "l"(a), "l"(b));
    return r;
}

// Branch-free ball-query push: predicated STS + predicated increment (no BSSY).
__device__ __forceinline__ void hit_push(unsigned int base, int& c, float d, int m) {
    unsigned short mh = (unsigned short)m;
    asm volatile("{\n\t"
        ".reg .pred p;\n\t"
        ".reg .b32 a;\n\t"
        "setp.lt.f32 p, %2, %4;\n\t"
        "setp.lt.and.s32 p, %0, 32, p;\n\t"
        "shl.b32 a, %0, 1;\n\t"
        "add.s32 a, a, %1;\n\t"
        "@p st.shared.u16 [a], %3;\n\t"
        "@p add.s32 %0, %0, 1;\n\t"
        "}"
        : "+r"(c)
        : "r"(base), "f"(d), "h"(mh), "f"(R2));
}

// ---------------- fused distance scan + F precompute ----------------
// blocks [0,256): dist row task (32 pts/block, m split over 8 warps, f32x2 packed)
// blocks [256,512): dist col task
// blocks [512,544): F GEMM blocks (256 m-values x all 128 outputs)
#define DIST_SMEM (2048 * 16 * 2 + 8 * 32 * 32 * 2 + 8 * 32 * 4 * 2 + 32 * 4)
__global__ void __launch_bounds__(256, 2) distf_kernel(
    const float* __restrict__ points, const float* __restrict__ knnpoints,
    const float* __restrict__ feat, const float* __restrict__ w1,
    const float* __restrict__ b1)
{
    extern __shared__ __align__(16) unsigned char smem_raw[];
    int t = threadIdx.x;

    if (blockIdx.x >= 512) {
        // ================= F precompute path (proven) =================
        float* sw = (float*)smem_raw;     // 8192 floats
        float* sb = sw + 8192;            // 128 floats
        int fbid = blockIdx.x - 512;      // 0..31
        if (fbid == 0 && t == 0) g_counter = 0u;
        for (int e = t; e < 8192; e += 256) {
            int o = e >> 6, c = e & 63;
            sw[(c * 8 + (o >> 4)) * 16 + (o & 15)] = w1[o * 68 + c];
        }
        if (t < 128) sb[t] = b1[t];
        __syncthreads();

        int og   = t >> 5;
        int lane = t & 31;
        const unsigned long long* sbv = (const unsigned long long*)(sb + og * 16);
        int idx_base = fbid * 256;
        int b     = idx_base >> 12;
        int mbase = idx_base & 4095;
        const float* fb = feat + ((size_t)b * 64) * 4096;

#pragma unroll
        for (int it = 0; it < 2; it++) {
            int mloc = it * 128 + lane * 4;
            unsigned long long acc[4][8];
#pragma unroll
            for (int mi = 0; mi < 4; mi++)
#pragma unroll
                for (int k = 0; k < 8; k++) acc[mi][k] = sbv[k];

            const float* fp = fb + mbase + mloc;
#pragma unroll 8
            for (int c = 0; c < 64; c++) {
                float4 f4 = *(const float4*)(fp + c * 4096);
                const unsigned long long* wv =
                    (const unsigned long long*)(sw + (c * 8 + og) * 16);
                unsigned long long x0 = packdup(f4.x), x1 = packdup(f4.y);
                unsigned long long x2 = packdup(f4.z), x3 = packdup(f4.w);
#pragma unroll
                for (int k = 0; k < 8; k++) {
                    unsigned long long wq = wv[k];
                    fma2(acc[0][k], wq, x0);
                    fma2(acc[1][k], wq, x1);
                    fma2(acc[2][k], wq, x2);
                    fma2(acc[3][k], wq, x3);
                }
            }
#pragma unroll
            for (int mi = 0; mi < 4; mi++) {
                float4* dst = (float4*)(g_F + ((size_t)(idx_base + mloc + mi)) * 128 + og * 16);
#pragma unroll
                for (int k = 0; k < 4; k++) {
                    float a0, a1, a2, a3;
                    unpack2(acc[mi][2 * k], a0, a1);
                    unpack2(acc[mi][2 * k + 1], a2, a3);
                    dst[k] = make_float4(a0, a1, a2, a3);
                }
            }
        }
        return;
    }

    // ================= distance path: broadcast + f32x2, branch-free ======
    float4*         shA  = (float4*)smem_raw;                // 2048 pairs (qx,qy)
    float4*         shB  = shA + 2048;                       // 2048 pairs (qz,qw)
    unsigned short* buf  = (unsigned short*)(shB + 2048);    // [w][lane][32]
    float*          cmin = (float*)(buf + 8 * 32 * 32);      // [w][lane]
    int*            ccnt = (int*)(cmin + 8 * 32);            // [w][lane]
    float*          red  = (float*)(ccnt + 8 * 32);          // [32]

    int  w    = t >> 5;               // warp = m-range 0..7
    int  lane = t & 31;               // lane = point slot 0..31
    bool row  = blockIdx.x < 256;
    int  ib   = row ? blockIdx.x : blockIdx.x - 256;
    int  i    = ib * 32 + lane;       // point index (b uniform per block)
    int  b    = i >> 12;
    int  x    = i & 4095;

    // build packed tile: per pair p -> A={qx0,qx1,qy0,qy1}, B={qz0,qz1,qw0,qw1}
    const float* scan = row ? knnpoints : points;
    for (int p = t; p < 2048; p += 256) {
        int m = 2 * p;
        float2 qx = *(const float2*)(scan + (b * 3 + 0) * 4096 + m);
        float2 qy = *(const float2*)(scan + (b * 3 + 1) * 4096 + m);
        float2 qz = *(const float2*)(scan + (b * 3 + 2) * 4096 + m);
        float w0 = fmaf(qx.x, qx.x, fmaf(qy.x, qy.x, qz.x * qz.x));
        float w1n = fmaf(qx.y, qx.y, fmaf(qy.y, qy.y, qz.y * qz.y));
        shA[p] = make_float4(qx.x, qx.y, qy.x, qy.y);
        shB[p] = make_float4(qz.x, qz.y, w0, w1n);
    }
    __syncthreads();

    const float* own = row ? points : knnpoints;
    float px = own[(b * 3 + 0) * 4096 + x];
    float py = own[(b * 3 + 1) * 4096 + x];
    float pz = own[(b * 3 + 2) * 4096 + x];
    float pe = fmaf(px, px, fmaf(py, py, pz * pz));

    unsigned long long pxd = packdup(px), pyd = packdup(py), pzd = packdup(pz);
    unsigned long long ped = packdup(pe), n2d = packdup(-2.0f);

    float minv0 = 3.402823e38f, minv1 = 3.402823e38f;
    int   c    = 0;
    unsigned short* mybuf = buf + (w * 32 + lane) * 32;
    unsigned int bufaddr = (unsigned int)__cvta_generic_to_shared(mybuf);

    int plo = w * 256, phi = plo + 256;   // 256 pairs = 512 m per warp
    if (row) {
        for (int p0 = plo; p0 < phi; p0 += 4) {
            ulonglong2 Av[4], Bv[4];
#pragma unroll
            for (int u = 0; u < 4; u++) {
                Av[u] = *(const ulonglong2*)(shA + p0 + u);
                Bv[u] = *(const ulonglong2*)(shB + p0 + u);
            }
#pragma unroll
            for (int u = 0; u < 4; u++) {
                unsigned long long dot2 = mul2(pzd, Bv[u].x);
                fma2(dot2, pyd, Av[u].y);
                fma2(dot2, pxd, Av[u].x);
                unsigned long long d2p = add2(ped, Bv[u].y);
                fma2(d2p, n2d, dot2);
                float d0, d1;
                unpack2(d2p, d0, d1);
                if (u & 1) minv1 = fminf(minv1, fminf(d0, d1));
                else       minv0 = fminf(minv0, fminf(d0, d1));
                int m0 = 2 * (p0 + u);
                hit_push(bufaddr, c, d0, m0);
                hit_push(bufaddr, c, d1, m0 + 1);
            }
        }
    } else {
        for (int p0 = plo; p0 < phi; p0 += 4) {
            ulonglong2 Av[4], Bv[4];
#pragma unroll
            for (int u = 0; u < 4; u++) {
                Av[u] = *(const ulonglong2*)(shA + p0 + u);
                Bv[u] = *(const ulonglong2*)(shB + p0 + u);
            }
#pragma unroll
            for (int u = 0; u < 4; u++) {
                unsigned long long dot2 = mul2(pzd, Bv[u].x);
                fma2(dot2, pyd, Av[u].y);
                fma2(dot2, pxd, Av[u].x);
                unsigned long long d2p = add2(ped, Bv[u].y);
                fma2(d2p, n2d, dot2);
                float d0, d1;
                unpack2(d2p, d0, d1);
                if (u & 1) minv1 = fminf(minv1, fminf(d0, d1));
                else       minv0 = fminf(minv0, fminf(d0, d1));
            }
        }
    }
    float minv = fminf(minv0, minv1);

    cmin[w * 32 + lane] = minv;
    ccnt[w * 32 + lane] = c;
    __syncthreads();

    if (row) {
        // prefix-merge hits across the 8 m-range warps (ascending m preserved)
        int pre = 0, tot = 0;
#pragma unroll
        for (int k = 0; k < 8; k++) {
            int ck = ccnt[k * 32 + lane];
            tot += ck;
            if (k < w) pre += ck;
        }
        int base = i * KK;
        for (int ii = 0; ii < c; ii++) {
            int pos = pre + ii;
            if (pos < KK) g_idx[base + pos] = (int)mybuf[ii];
        }
        if (w == 0) {
            int cnt = tot < KK ? tot : KK;
            g_cnt[i] = cnt;
            if (cnt == 0) g_idx[base] = 0;
        }
    }
    if (w == 0) {
        float mv = cmin[lane];
#pragma unroll
        for (int k = 1; k < 8; k++) mv = fminf(mv, cmin[k * 32 + lane]);
        mv = fmaxf(mv, 0.0f);   // clamp-before-min == max(rawmin, 0)
        red[lane] = sqrtf(1e-6f + mv);
    }
    __syncthreads();
    if (t < 32) {
        float s = red[t];
#pragma unroll
        for (int off = 16; off > 0; off >>= 1) s += __shfl_xor_sync(0xffffffffu, s, off);
        if (t == 0) {
            if (row) g_rowpart[ib] = s;
            else     g_colpart[ib] = s;
        }
    }
}

// ---------------- dense column-stream MLP (R13/R15-proven: 20 warps) --------
#define NWARP 20
#define NTHR  640
#define OFF_W2 0
#define OFF_W3 8192
#define OFF_B2 12288
#define OFF_B3 12352
#define OFF_WD1 12416
#define OFF_WARP 13440
#define OFF_H1 64
#define OFF_H2 1088
#define WARP_STRIDE 1600
#define SMEM_FLOATS (OFF_WARP + NWARP * WARP_STRIDE)

__global__ void __launch_bounds__(NTHR, 1) mlp_kernel(
    const float* __restrict__ points, const float* __restrict__ knnpoints,
    const float* __restrict__ w1,
    const float* __restrict__ w2, const float* __restrict__ b2,
    const float* __restrict__ w3, const float* __restrict__ b3,
    float* __restrict__ out)
{
    extern __shared__ __align__(16) unsigned char smem_raw2[];
    float* sm = (float*)smem_raw2;
    int tid = threadIdx.x;

    // W2 packed
    for (int e = tid; e < 64 * 128; e += NTHR) {
        int c2 = e >> 7, z = e & 127, l = z >> 2, s = z & 3;
        int c = 2 * c2 + (s >> 1), o = 2 * l + (s & 1);
        sm[OFF_W2 + e] = w2[o * 128 + c];
    }
    // W3 packed
    for (int e = tid; e < 64 * 64; e += NTHR) {
        int c2 = e >> 7, z = e & 127, l = z >> 2, s = z & 3;
        int c = 2 * c2 + (s >> 1), o = 2 * l + (s & 1);
        sm[OFF_W3 + e] = w3[o * 64 + c];
    }
    if (tid < 64) sm[OFF_B2 + tid] = b2[tid];
    if (tid < 64) sm[OFF_B3 + tid] = b3[tid];
    // WD1 table: u64[ch*128 + oo*32 + l]
    {
        unsigned long long* wd1t = (unsigned long long*)(sm + OFF_WD1);
        for (int e = tid; e < 512; e += NTHR) {
            int ch = e >> 7, r = e & 127, oo = r >> 5, l = r & 31;
            wd1t[e] = packdup(w1[(4 * l + oo) * 68 + 64 + ch]);
        }
    }
    __syncthreads();

    int lane = tid & 31;
    int wrp  = tid >> 5;
    float* ws  = sm + OFF_WARP + wrp * WARP_STRIDE;
    float* h1p = ws + OFF_H1;
    float* h2p = ws + OFF_H2;
    int*   smm  = (int*)ws;
    int*   smi  = (int*)(ws + 8);
    float* smw  = ws + 16;
    int*   smnp = (int*)(ws + 24);
    const float4* w2q = (const float4*)(sm + OFF_W2);
    const float4* w3q = (const float4*)(sm + OFF_W3);
    const unsigned long long* wd1t = (const unsigned long long*)(sm + OFF_WD1);

    float bb2_0 = sm[OFF_B2 + 2 * lane], bb2_1 = sm[OFF_B2 + 2 * lane + 1];
    float bb3_0 = sm[OFF_B3 + 2 * lane], bb3_1 = sm[OFF_B3 + 2 * lane + 1];

    // stream state (warp-uniform)
    int cur_i = 0, cur_cols = 0, cur_j = 0;
    int open_i = -1;
    float agg0 = 0.f, agg1 = 0.f;

    for (;;) {
        // ---- fill up to 8 slots from the column stream ----
        int nslots = 0;
        while (nslots < 8) {
            if (cur_j >= cur_cols) {
                int ni = 0;
                if (lane == 0) ni = (int)atomicAdd(&g_counter, 1u);
                ni = __shfl_sync(0xffffffffu, ni, 0);
                if (ni >= Bsz * Npts) { cur_cols = 0; cur_j = 0; break; }
                cur_i = ni;
                int cc = g_cnt[ni];
                cur_cols = cc > 0 ? cc : 1;
                cur_j = 0;
            }
            int take = cur_cols - cur_j;
            if (take > 8 - nslots) take = 8 - nslots;
            if (lane < take) {
                int slot = nslots + lane;
                int j = cur_j + lane;
                int m = g_idx[cur_i * KK + j];
                int b = cur_i >> 12, n = cur_i & 4095;
                smm[slot] = m;
                smi[slot] = cur_i;
                smw[slot] = (j == 0) ? (float)(KK - cur_cols + 1) : 1.0f;
                smnp[slot] = (j == 0) ? 1 : 0;
                float ppx = points[(b * 3 + 0) * 4096 + n];
                float ppy = points[(b * 3 + 1) * 4096 + n];
                float ppz = points[(b * 3 + 2) * 4096 + n];
                float qx = knnpoints[(b * 3 + 0) * 4096 + m];
                float qy = knnpoints[(b * 3 + 1) * 4096 + m];
                float qz = knnpoints[(b * 3 + 2) * 4096 + m];
                float dx = qx - ppx, dy = qy - ppy, dz = qz - ppz;
                float dd = fmaf(dx, dx, fmaf(dy, dy, dz * dz));
                ws[32 + 0 * 8 + slot] = dx;
                ws[32 + 1 * 8 + slot] = dy;
                ws[32 + 2 * 8 + slot] = dz;
                ws[32 + 3 * 8 + slot] = dd;
            }
            nslots += take;
            cur_j += take;
        }
        __syncwarp();
        if (nslots == 0) break;
        if (nslots < 8) {
            // pad with zero-weight copies of the last real slot (finite operands)
            if (lane >= nslots && lane < 8) {
                int src = nslots - 1;
                smm[lane] = smm[src];
                smi[lane] = smi[src];
                smw[lane] = 0.0f;
                smnp[lane] = 0;
                ws[32 + 0 * 8 + lane] = ws[32 + 0 * 8 + src];
                ws[32 + 1 * 8 + lane] = ws[32 + 1 * 8 + src];
                ws[32 + 2 * 8 + lane] = ws[32 + 2 * 8 + src];
                ws[32 + 3 * 8 + lane] = ws[32 + 3 * 8 + src];
            }
            __syncwarp();
        }

        // ---- layer 1: F[m] + W1d·diff (4 channels), o = 4lane..+3 ----
        {
            float4 Fv[8];
#pragma unroll
            for (int j = 0; j < 8; j++) {
                int m = smm[j];
                int bidx = smi[j] >> 12;
                Fv[j] = *(const float4*)(g_F + ((size_t)((bidx << 12) + m)) * 128 + 4 * lane);
            }
            unsigned long long xch[4][4];
#pragma unroll
            for (int ch = 0; ch < 4; ch++)
#pragma unroll
                for (int jp = 0; jp < 4; jp++)
                    xch[ch][jp] = *(const unsigned long long*)(ws + 32 + ch * 8 + 2 * jp);

            unsigned long long acc[4][4];
#pragma unroll
            for (int jp = 0; jp < 4; jp++) {
                acc[jp][0] = pack2(Fv[2 * jp].x, Fv[2 * jp + 1].x);
                acc[jp][1] = pack2(Fv[2 * jp].y, Fv[2 * jp + 1].y);
                acc[jp][2] = pack2(Fv[2 * jp].z, Fv[2 * jp + 1].z);
                acc[jp][3] = pack2(Fv[2 * jp].w, Fv[2 * jp + 1].w);
            }
#pragma unroll
            for (int ch = 0; ch < 4; ch++) {
                unsigned long long w0 = wd1t[ch * 128 + 0  + lane];
                unsigned long long w1r = wd1t[ch * 128 + 32 + lane];
                unsigned long long w2r = wd1t[ch * 128 + 64 + lane];
                unsigned long long w3r = wd1t[ch * 128 + 96 + lane];
#pragma unroll
                for (int jp = 0; jp < 4; jp++) {
                    fma2(acc[jp][0], w0,  xch[ch][jp]);
                    fma2(acc[jp][1], w1r, xch[ch][jp]);
                    fma2(acc[jp][2], w2r, xch[ch][jp]);
                    fma2(acc[jp][3], w3r, xch[ch][jp]);
                }
            }

            int u0 = 2 * lane, u1 = 2 * lane + 1;
            int p0 = u0 ^ ((u0 >> 3) & 7);
            int p1 = u1 ^ ((u1 >> 3) & 7);
#pragma unroll
            for (int jp = 0; jp < 4; jp++) {
                float v0, v1, v2, v3;
                unpack2(acc[jp][0], v0, v1);
                unpack2(acc[jp][1], v2, v3);
                *(float4*)(h1p + jp * 256 + p0 * 4) =
                    make_float4(fmaxf(v0, 0.f), fmaxf(v1, 0.f), fmaxf(v2, 0.f), fmaxf(v3, 0.f));
                unpack2(acc[jp][2], v0, v1);
                unpack2(acc[jp][3], v2, v3);
                *(float4*)(h1p + jp * 256 + p1 * 4) =
                    make_float4(fmaxf(v0, 0.f), fmaxf(v1, 0.f), fmaxf(v2, 0.f), fmaxf(v3, 0.f));
            }
        }
        __syncwarp();
        // ---- layer 2: 128 -> 64, lane owns o = 2lane, 2lane+1 ----
        {
            unsigned long long acc[4][2];
#pragma unroll
            for (int jp = 0; jp < 4; jp++) {
                acc[jp][0] = packdup(bb2_0);
                acc[jp][1] = packdup(bb2_1);
            }
#pragma unroll
            for (int c4 = 0; c4 < 32; c4++) {
                float4 WA = w2q[(2 * c4) * 32 + lane];
                float4 WB = w2q[(2 * c4 + 1) * 32 + lane];
                unsigned long long wd[4][2];
                wd[0][0] = packdup(WA.x); wd[0][1] = packdup(WA.y);
                wd[1][0] = packdup(WA.z); wd[1][1] = packdup(WA.w);
                wd[2][0] = packdup(WB.x); wd[2][1] = packdup(WB.y);
                wd[3][0] = packdup(WB.z); wd[3][1] = packdup(WB.w);
                int ua = 2 * c4, ub = 2 * c4 + 1;
                int pa = ua ^ ((ua >> 3) & 7);
                int pb = ub ^ ((ub >> 3) & 7);
#pragma unroll
                for (int jp = 0; jp < 4; jp++) {
                    ulonglong2 XA = *(const ulonglong2*)(h1p + jp * 256 + pa * 4);
                    ulonglong2 XB = *(const ulonglong2*)(h1p + jp * 256 + pb * 4);
                    fma2(acc[jp][0], wd[0][0], XA.x); fma2(acc[jp][1], wd[0][1], XA.x);
                    fma2(acc[jp][0], wd[1][0], XA.y); fma2(acc[jp][1], wd[1][1], XA.y);
                    fma2(acc[jp][0], wd[2][0], XB.x); fma2(acc[jp][1], wd[2][1], XB.x);
                    fma2(acc[jp][0], wd[3][0], XB.y); fma2(acc[jp][1], wd[3][1], XB.y);
                }
            }
#pragma unroll
            for (int jp = 0; jp < 4; jp++) {
                float v0, v1, v2, v3;
                unpack2(acc[jp][0], v0, v1);
                unpack2(acc[jp][1], v2, v3);
                *(float4*)(h2p + jp * 128 + 4 * lane) =
                    make_float4(fmaxf(v0, 0.f), fmaxf(v1, 0.f), fmaxf(v2, 0.f), fmaxf(v3, 0.f));
            }
        }
        __syncwarp();
        // ---- layer 3: 64 -> 64 + streaming aggregate with point flush ----
        {
            unsigned long long acc[4][2];
#pragma unroll
            for (int jp = 0; jp < 4; jp++) {
                acc[jp][0] = packdup(bb3_0);
                acc[jp][1] = packdup(bb3_1);
            }
#pragma unroll
            for (int c4 = 0; c4 < 16; c4++) {
                float4 WA = w3q[(2 * c4) * 32 + lane];
                float4 WB = w3q[(2 * c4 + 1) * 32 + lane];
                unsigned long long wd[4][2];
                wd[0][0] = packdup(WA.x); wd[0][1] = packdup(WA.y);
                wd[1][0] = packdup(WA.z); wd[1][1] = packdup(WA.w);
                wd[2][0] = packdup(WB.x); wd[2][1] = packdup(WB.y);
                wd[3][0] = packdup(WB.z); wd[3][1] = packdup(WB.w);
#pragma unroll
                for (int jp = 0; jp < 4; jp++) {
                    ulonglong2 XA = *(const ulonglong2*)(h2p + jp * 128 + 8 * c4);
                    ulonglong2 XB = *(const ulonglong2*)(h2p + jp * 128 + 8 * c4 + 4);
                    fma2(acc[jp][0], wd[0][0], XA.x); fma2(acc[jp][1], wd[0][1], XA.x);
                    fma2(acc[jp][0], wd[1][0], XA.y); fma2(acc[jp][1], wd[1][1], XA.y);
                    fma2(acc[jp][0], wd[2][0], XB.x); fma2(acc[jp][1], wd[2][1], XB.x);
                    fma2(acc[jp][0], wd[3][0], XB.y); fma2(acc[jp][1], wd[3][1], XB.y);
                }
            }
#pragma unroll
            for (int jp = 0; jp < 4; jp++) {
                float v00, v01, v10, v11;
                unpack2(acc[jp][0], v00, v01);
                unpack2(acc[jp][1], v10, v11);
#pragma unroll
                for (int h = 0; h < 2; h++) {
                    int col = 2 * jp + h;
                    float va = h ? v01 : v00;
                    float vb = h ? v11 : v10;
                    if (smnp[col]) {
                        if (open_i >= 0) {
                            int fb = open_i >> 12, fn = open_i & 4095;
                            out[((size_t)(fb * 64 + 2 * lane + 0)) * 4096 + fn] = agg0;
                            out[((size_t)(fb * 64 + 2 * lane + 1)) * 4096 + fn] = agg1;
                        }
                        open_i = smi[col];
                        agg0 = 0.f; agg1 = 0.f;
                    }
                    float w = smw[col];
                    agg0 = fmaf(w, fmaxf(va, 0.f), agg0);
                    agg1 = fmaf(w, fmaxf(vb, 0.f), agg1);
                }
            }
        }
        __syncwarp();
    }

    // flush the last open point
    if (open_i >= 0) {
        int fb = open_i >> 12, fn = open_i & 4095;
        out[((size_t)(fb * 64 + 2 * lane + 0)) * 4096 + fn] = agg0;
        out[((size_t)(fb * 64 + 2 * lane + 1)) * 4096 + fn] = agg1;
    }

    // ---- folded loss reduction (depends only on dist results) ----
    if (blockIdx.x == 0 && tid < 32) {
        float s = 0.f;
        for (int t2 = tid; t2 < 256; t2 += 32) s += g_rowpart[t2] + g_colpart[t2];
#pragma unroll
        for (int off = 16; off > 0; off >>= 1) s += __shfl_xor_sync(0xffffffffu, s, off);
        if (tid == 0) out[Bsz * 64 * Npts] = s * (1.0f / 8192.0f);
    }
}

extern "C" void kernel_launch(void* const* d_in, const int* in_sizes, int n_in,
                              void* d_out, int out_size) {
    const float* points    = (const float*)d_in[0];
    const float* knnpoints = (const float*)d_in[1];
    const float* feat      = (const float*)d_in[2];
    const float* w1 = (const float*)d_in[3];
    const float* b1 = (const float*)d_in[4];
    const float* w2 = (const float*)d_in[5];
    const float* b2 = (const float*)d_in[6];
    const float* w3 = (const float*)d_in[7];
    const float* b3 = (const float*)d_in[8];
    float* out = (float*)d_out;

    cudaFuncSetAttribute(distf_kernel, cudaFuncAttributeMaxDynamicSharedMemorySize, DIST_SMEM);
    cudaFuncSetAttribute(mlp_kernel,   cudaFuncAttributeMaxDynamicSharedMemorySize, SMEM_FLOATS * 4);

    int nsm = 148;
    cudaDeviceGetAttribute(&nsm, cudaDevAttrMultiProcessorCount, 0);

    distf_kernel<<<544, 256, DIST_SMEM>>>(points, knnpoints, feat, w1, b1);
    mlp_kernel<<<nsm, NTHR, SMEM_FLOATS * 4>>>(points, knnpoints, w1, w2, b2, w3, b3, out);
}

// round 17
// speedup vs baseline: 2.7291x; 1.1221x over previous
#include <cuda_runtime.h>
#include <math.h>

#define Bsz 2
#define Npts 4096
#define Mpts 4096
#define KK 32
#define CC 64
#define R2 0.0064f

// ---------------- device scratch (no allocs allowed) ----------------
__device__ float g_F[Bsz * Mpts * 128];      // F[b][m][o] = W1[:, :64]·feat[b,:,m] + b1
__device__ int   g_idx[Bsz * Npts * KK];     // ball query indices (compacted)
__device__ int   g_cnt[Bsz * Npts];          // neighbor counts
__device__ float g_rowpart[256];             // per-block partial sums: min over m
__device__ float g_colpart[256];             // per-block partial sums: min over n
__device__ unsigned int g_counter;           // work queue for mlp kernel

// ---------------- packed f32x2 helpers ----------------
__device__ __forceinline__ unsigned long long packdup(float a) {
    unsigned long long r;
    asm("mov.b64 %0, {%1, %1};" : "=l"(r) : "f"(a));
    return r;
}
__device__ __forceinline__ unsigned long long pack2(float a, float b) {
    unsigned long long r;
    asm("mov.b64 %0, {%1, %2};" : "=l"(r) : "f"(a), "f"(b));
    return r;
}
__device__ __forceinline__ void unpack2(unsigned long long v, float& a, float& b) {
    asm("mov.b64 {%0, %1}, %2;" : "=f"(a), "=f"(b) : "l"(v));
}
__device__ __forceinline__ void fma2(unsigned long long& d, unsigned long long a,
                                     unsigned long long b) {
    asm("fma.rn.f32x2 %0, %1, %2, %0;" : "+l"(d) : "l"(a), "l"(b));
}
__device__ __forceinline__ unsigned long long mul2(unsigned long long a,
                                                   unsigned long long b) {
    unsigned long long r;
    asm("mul.rn.f32x2 %0, %1, %2;" : "=l"(r) : "l"(a), "l"(b));
    return r;
}
__device__ __forceinline__ unsigned long long add2(unsigned long long a,
                                                   unsigned long long b) {
    unsigned long long r;
    asm("add.rn.f32x2 %0, %1, %2;" : "=l"(r) : "l"(a), "l"(b));
    return r;
}

// Branch-free ball-query push: predicated STS + predicated increment (no BSSY).
__device__ __forceinline__ void hit_push(unsigned int base, int& c, float d, int m) {
    unsigned short mh = (unsigned short)m;
    asm volatile("{\n\t"
        ".reg .pred p;\n\t"
        ".reg .b32 a;\n\t"
        "setp.lt.f32 p, %2, %4;\n\t"
        "setp.lt.and.s32 p, %0, 32, p;\n\t"
        "shl.b32 a, %0, 1;\n\t"
        "add.s32 a, a, %1;\n\t"
        "@p st.shared.u16 [a], %3;\n\t"
        "@p add.s32 %0, %0, 1;\n\t"
        "}"
        : "+r"(c)
        : "r"(base), "f"(d), "h"(mh), "f"(R2));
}

// ---------------- fused F precompute + distance scan ----------------
// blocks [0,128):   F GEMM blocks, SCHEDULED FIRST (64 m-values x 128 outputs each)
// blocks [128,384): dist row task (32 pts/block, m split over 8 warps, f32x2 packed)
// blocks [384,640): dist col task
#define DIST_SMEM (2048 * 16 * 2 + 8 * 32 * 32 * 2 + 8 * 32 * 4 * 2 + 32 * 4)
__global__ void __launch_bounds__(256, 2) distf_kernel(
    const float* __restrict__ points, const float* __restrict__ knnpoints,
    const float* __restrict__ feat, const float* __restrict__ w1,
    const float* __restrict__ b1)
{
    extern __shared__ __align__(16) unsigned char smem_raw[];
    int t = threadIdx.x;

    if (blockIdx.x < 128) {
        // ================= F precompute path (128 blocks, wave-1) ==========
        float* sw = (float*)smem_raw;     // 8192 floats
        float* sb = sw + 8192;            // 128 floats
        int fbid = blockIdx.x;            // 0..127
        if (fbid == 0 && t == 0) g_counter = 0u;
        for (int e = t; e < 8192; e += 256) {
            int o = e >> 6, c = e & 63;
            sw[(c * 8 + (o >> 4)) * 16 + (o & 15)] = w1[o * 68 + c];
        }
        if (t < 128) sb[t] = b1[t];
        __syncthreads();

        int og   = t >> 5;                // warp = o-group (16 outputs)
        int lane = t & 31;
        const unsigned long long* sbv = (const unsigned long long*)(sb + og * 16);
        int idx_base = fbid * 64;
        int b     = idx_base >> 12;
        int mbase = idx_base & 4095;
        const float* fb = feat + ((size_t)b * 64) * 4096;

        int mloc = lane * 2;              // 2 m per lane -> 64 m per block
        unsigned long long acc[2][8];
#pragma unroll
        for (int mi = 0; mi < 2; mi++)
#pragma unroll
            for (int k = 0; k < 8; k++) acc[mi][k] = sbv[k];

        const float* fp = fb + mbase + mloc;
#pragma unroll 8
        for (int c = 0; c < 64; c++) {
            float2 f2 = *(const float2*)(fp + c * 4096);
            const unsigned long long* wv =
                (const unsigned long long*)(sw + (c * 8 + og) * 16);
            unsigned long long x0 = packdup(f2.x), x1 = packdup(f2.y);
#pragma unroll
            for (int k = 0; k < 8; k++) {
                unsigned long long wq = wv[k];
                fma2(acc[0][k], wq, x0);
                fma2(acc[1][k], wq, x1);
            }
        }
#pragma unroll
        for (int mi = 0; mi < 2; mi++) {
            float4* dst = (float4*)(g_F + ((size_t)(idx_base + mloc + mi)) * 128 + og * 16);
#pragma unroll
            for (int k = 0; k < 4; k++) {
                float a0, a1, a2, a3;
                unpack2(acc[mi][2 * k], a0, a1);
                unpack2(acc[mi][2 * k + 1], a2, a3);
                dst[k] = make_float4(a0, a1, a2, a3);
            }
        }
        return;
    }

    // ================= distance path: broadcast + f32x2, branch-free ======
    float4*         shA  = (float4*)smem_raw;                // 2048 pairs (qx,qy)
    float4*         shB  = shA + 2048;                       // 2048 pairs (qz,qw)
    unsigned short* buf  = (unsigned short*)(shB + 2048);    // [w][lane][32]
    float*          cmin = (float*)(buf + 8 * 32 * 32);      // [w][lane]
    int*            ccnt = (int*)(cmin + 8 * 32);            // [w][lane]
    float*          red  = (float*)(ccnt + 8 * 32);          // [32]

    int  w    = t >> 5;               // warp = m-range 0..7
    int  lane = t & 31;               // lane = point slot 0..31
    bool row  = blockIdx.x < 384;
    int  ib   = row ? (blockIdx.x - 128) : (blockIdx.x - 384);
    int  i    = ib * 32 + lane;       // point index (b uniform per block)
    int  b    = i >> 12;
    int  x    = i & 4095;

    // build packed tile: per pair p -> A={qx0,qx1,qy0,qy1}, B={qz0,qz1,qw0,qw1}
    const float* scan = row ? knnpoints : points;
    for (int p = t; p < 2048; p += 256) {
        int m = 2 * p;
        float2 qx = *(const float2*)(scan + (b * 3 + 0) * 4096 + m);
        float2 qy = *(const float2*)(scan + (b * 3 + 1) * 4096 + m);
        float2 qz = *(const float2*)(scan + (b * 3 + 2) * 4096 + m);
        float w0 = fmaf(qx.x, qx.x, fmaf(qy.x, qy.x, qz.x * qz.x));
        float w1n = fmaf(qx.y, qx.y, fmaf(qy.y, qy.y, qz.y * qz.y));
        shA[p] = make_float4(qx.x, qx.y, qy.x, qy.y);
        shB[p] = make_float4(qz.x, qz.y, w0, w1n);
    }
    __syncthreads();

    const float* own = row ? points : knnpoints;
    float px = own[(b * 3 + 0) * 4096 + x];
    float py = own[(b * 3 + 1) * 4096 + x];
    float pz = own[(b * 3 + 2) * 4096 + x];
    float pe = fmaf(px, px, fmaf(py, py, pz * pz));

    unsigned long long pxd = packdup(px), pyd = packdup(py), pzd = packdup(pz);
    unsigned long long ped = packdup(pe), n2d = packdup(-2.0f);

    float minv0 = 3.402823e38f, minv1 = 3.402823e38f;
    int   c    = 0;
    unsigned short* mybuf = buf + (w * 32 + lane) * 32;
    unsigned int bufaddr = (unsigned int)__cvta_generic_to_shared(mybuf);

    int plo = w * 256, phi = plo + 256;   // 256 pairs = 512 m per warp
    if (row) {
        for (int p0 = plo; p0 < phi; p0 += 4) {
            ulonglong2 Av[4], Bv[4];
#pragma unroll
            for (int u = 0; u < 4; u++) {
                Av[u] = *(const ulonglong2*)(shA + p0 + u);
                Bv[u] = *(const ulonglong2*)(shB + p0 + u);
            }
#pragma unroll
            for (int u = 0; u < 4; u++) {
                unsigned long long dot2 = mul2(pzd, Bv[u].x);
                fma2(dot2, pyd, Av[u].y);
                fma2(dot2, pxd, Av[u].x);
                unsigned long long d2p = add2(ped, Bv[u].y);
                fma2(d2p, n2d, dot2);
                float d0, d1;
                unpack2(d2p, d0, d1);
                if (u & 1) minv1 = fminf(minv1, fminf(d0, d1));
                else       minv0 = fminf(minv0, fminf(d0, d1));
                int m0 = 2 * (p0 + u);
                hit_push(bufaddr, c, d0, m0);
                hit_push(bufaddr, c, d1, m0 + 1);
            }
        }
    } else {
        for (int p0 = plo; p0 < phi; p0 += 4) {
            ulonglong2 Av[4], Bv[4];
#pragma unroll
            for (int u = 0; u < 4; u++) {
                Av[u] = *(const ulonglong2*)(shA + p0 + u);
                Bv[u] = *(const ulonglong2*)(shB + p0 + u);
            }
#pragma unroll
            for (int u = 0; u < 4; u++) {
                unsigned long long dot2 = mul2(pzd, Bv[u].x);
                fma2(dot2, pyd, Av[u].y);
                fma2(dot2, pxd, Av[u].x);
                unsigned long long d2p = add2(ped, Bv[u].y);
                fma2(d2p, n2d, dot2);
                float d0, d1;
                unpack2(d2p, d0, d1);
                if (u & 1) minv1 = fminf(minv1, fminf(d0, d1));
                else       minv0 = fminf(minv0, fminf(d0, d1));
            }
        }
    }
    float minv = fminf(minv0, minv1);

    cmin[w * 32 + lane] = minv;
    ccnt[w * 32 + lane] = c;
    __syncthreads();

    if (row) {
        // prefix-merge hits across the 8 m-range warps (ascending m preserved)
        int pre = 0, tot = 0;
#pragma unroll
        for (int k = 0; k < 8; k++) {
            int ck = ccnt[k * 32 + lane];
            tot += ck;
            if (k < w) pre += ck;
        }
        int base = i * KK;
        for (int ii = 0; ii < c; ii++) {
            int pos = pre + ii;
            if (pos < KK) g_idx[base + pos] = (int)mybuf[ii];
        }
        if (w == 0) {
            int cnt = tot < KK ? tot : KK;
            g_cnt[i] = cnt;
            if (cnt == 0) g_idx[base] = 0;
        }
    }
    if (w == 0) {
        float mv = cmin[lane];
#pragma unroll
        for (int k = 1; k < 8; k++) mv = fminf(mv, cmin[k * 32 + lane]);
        mv = fmaxf(mv, 0.0f);   // clamp-before-min == max(rawmin, 0)
        red[lane] = sqrtf(1e-6f + mv);
    }
    __syncthreads();
    if (t < 32) {
        float s = red[t];
#pragma unroll
        for (int off = 16; off > 0; off >>= 1) s += __shfl_xor_sync(0xffffffffu, s, off);
        if (t == 0) {
            if (row) g_rowpart[ib] = s;
            else     g_colpart[ib] = s;
        }
    }
}

// ---------------- dense column-stream MLP (R13/R15-proven: 20 warps) --------
#define NWARP 20
#define NTHR  640
#define OFF_W2 0
#define OFF_W3 8192
#define OFF_B2 12288
#define OFF_B3 12352
#define OFF_WD1 12416
#define OFF_WARP 13440
#define OFF_H1 64
#define OFF_H2 1088
#define WARP_STRIDE 1600
#define SMEM_FLOATS (OFF_WARP + NWARP * WARP_STRIDE)

__global__ void __launch_bounds__(NTHR, 1) mlp_kernel(
    const float* __restrict__ points, const float* __restrict__ knnpoints,
    const float* __restrict__ w1,
    const float* __restrict__ w2, const float* __restrict__ b2,
    const float* __restrict__ w3, const float* __restrict__ b3,
    float* __restrict__ out)
{
    extern __shared__ __align__(16) unsigned char smem_raw2[];
    float* sm = (float*)smem_raw2;
    int tid = threadIdx.x;

    // W2 packed
    for (int e = tid; e < 64 * 128; e += NTHR) {
        int c2 = e >> 7, z = e & 127, l = z >> 2, s = z & 3;
        int c = 2 * c2 + (s >> 1), o = 2 * l + (s & 1);
        sm[OFF_W2 + e] = w2[o * 128 + c];
    }
    // W3 packed
    for (int e = tid; e < 64 * 64; e += NTHR) {
        int c2 = e >> 7, z = e & 127, l = z >> 2, s = z & 3;
        int c = 2 * c2 + (s >> 1), o = 2 * l + (s & 1);
        sm[OFF_W3 + e] = w3[o * 64 + c];
    }
    if (tid < 64) sm[OFF_B2 + tid] = b2[tid];
    if (tid < 64) sm[OFF_B3 + tid] = b3[tid];
    // WD1 table: u64[ch*128 + oo*32 + l]
    {
        unsigned long long* wd1t = (unsigned long long*)(sm + OFF_WD1);
        for (int e = tid; e < 512; e += NTHR) {
            int ch = e >> 7, r = e & 127, oo = r >> 5, l = r & 31;
            wd1t[e] = packdup(w1[(4 * l + oo) * 68 + 64 + ch]);
        }
    }
    __syncthreads();

    int lane = tid & 31;
    int wrp  = tid >> 5;
    float* ws  = sm + OFF_WARP + wrp * WARP_STRIDE;
    float* h1p = ws + OFF_H1;
    float* h2p = ws + OFF_H2;
    int*   smm  = (int*)ws;
    int*   smi  = (int*)(ws + 8);
    float* smw  = ws + 16;
    int*   smnp = (int*)(ws + 24);
    const float4* w2q = (const float4*)(sm + OFF_W2);
    const float4* w3q = (const float4*)(sm + OFF_W3);
    const unsigned long long* wd1t = (const unsigned long long*)(sm + OFF_WD1);

    float bb2_0 = sm[OFF_B2 + 2 * lane], bb2_1 = sm[OFF_B2 + 2 * lane + 1];
    float bb3_0 = sm[OFF_B3 + 2 * lane], bb3_1 = sm[OFF_B3 + 2 * lane + 1];

    // stream state (warp-uniform)
    int cur_i = 0, cur_cols = 0, cur_j = 0;
    int open_i = -1;
    float agg0 = 0.f, agg1 = 0.f;

    for (;;) {
        // ---- fill up to 8 slots from the column stream ----
        int nslots = 0;
        while (nslots < 8) {
            if (cur_j >= cur_cols) {
                int ni = 0;
                if (lane == 0) ni = (int)atomicAdd(&g_counter, 1u);
                ni = __shfl_sync(0xffffffffu, ni, 0);
                if (ni >= Bsz * Npts) { cur_cols = 0; cur_j = 0; break; }
                cur_i = ni;
                int cc = g_cnt[ni];
                cur_cols = cc > 0 ? cc : 1;
                cur_j = 0;
            }
            int take = cur_cols - cur_j;
            if (take > 8 - nslots) take = 8 - nslots;
            if (lane < take) {
                int slot = nslots + lane;
                int j = cur_j + lane;
                int m = g_idx[cur_i * KK + j];
                int b = cur_i >> 12, n = cur_i & 4095;
                smm[slot] = m;
                smi[slot] = cur_i;
                smw[slot] = (j == 0) ? (float)(KK - cur_cols + 1) : 1.0f;
                smnp[slot] = (j == 0) ? 1 : 0;
                float ppx = points[(b * 3 + 0) * 4096 + n];
                float ppy = points[(b * 3 + 1) * 4096 + n];
                float ppz = points[(b * 3 + 2) * 4096 + n];
                float qx = knnpoints[(b * 3 + 0) * 4096 + m];
                float qy = knnpoints[(b * 3 + 1) * 4096 + m];
                float qz = knnpoints[(b * 3 + 2) * 4096 + m];
                float dx = qx - ppx, dy = qy - ppy, dz = qz - ppz;
                float dd = fmaf(dx, dx, fmaf(dy, dy, dz * dz));
                ws[32 + 0 * 8 + slot] = dx;
                ws[32 + 1 * 8 + slot] = dy;
                ws[32 + 2 * 8 + slot] = dz;
                ws[32 + 3 * 8 + slot] = dd;
            }
            nslots += take;
            cur_j += take;
        }
        __syncwarp();
        if (nslots == 0) break;
        if (nslots < 8) {
            // pad with zero-weight copies of the last real slot (finite operands)
            if (lane >= nslots && lane < 8) {
                int src = nslots - 1;
                smm[lane] = smm[src];
                smi[lane] = smi[src];
                smw[lane] = 0.0f;
                smnp[lane] = 0;
                ws[32 + 0 * 8 + lane] = ws[32 + 0 * 8 + src];
                ws[32 + 1 * 8 + lane] = ws[32 + 1 * 8 + src];
                ws[32 + 2 * 8 + lane] = ws[32 + 2 * 8 + src];
                ws[32 + 3 * 8 + lane] = ws[32 + 3 * 8 + src];
            }
            __syncwarp();
        }

        // ---- layer 1: F[m] + W1d·diff (4 channels), o = 4lane..+3 ----
        {
            float4 Fv[8];
#pragma unroll
            for (int j = 0; j < 8; j++) {
                int m = smm[j];
                int bidx = smi[j] >> 12;
                Fv[j] = *(const float4*)(g_F + ((size_t)((bidx << 12) + m)) * 128 + 4 * lane);
            }
            unsigned long long xch[4][4];
#pragma unroll
            for (int ch = 0; ch < 4; ch++)
#pragma unroll
                for (int jp = 0; jp < 4; jp++)
                    xch[ch][jp] = *(const unsigned long long*)(ws + 32 + ch * 8 + 2 * jp);

            unsigned long long acc[4][4];
#pragma unroll
            for (int jp = 0; jp < 4; jp++) {
                acc[jp][0] = pack2(Fv[2 * jp].x, Fv[2 * jp + 1].x);
                acc[jp][1] = pack2(Fv[2 * jp].y, Fv[2 * jp + 1].y);
                acc[jp][2] = pack2(Fv[2 * jp].z, Fv[2 * jp + 1].z);
                acc[jp][3] = pack2(Fv[2 * jp].w, Fv[2 * jp + 1].w);
            }
#pragma unroll
            for (int ch = 0; ch < 4; ch++) {
                unsigned long long w0 = wd1t[ch * 128 + 0  + lane];
                unsigned long long w1r = wd1t[ch * 128 + 32 + lane];
                unsigned long long w2r = wd1t[ch * 128 + 64 + lane];
                unsigned long long w3r = wd1t[ch * 128 + 96 + lane];
#pragma unroll
                for (int jp = 0; jp < 4; jp++) {
                    fma2(acc[jp][0], w0,  xch[ch][jp]);
                    fma2(acc[jp][1], w1r, xch[ch][jp]);
                    fma2(acc[jp][2], w2r, xch[ch][jp]);
                    fma2(acc[jp][3], w3r, xch[ch][jp]);
                }
            }

            int u0 = 2 * lane, u1 = 2 * lane + 1;
            int p0 = u0 ^ ((u0 >> 3) & 7);
            int p1 = u1 ^ ((u1 >> 3) & 7);
#pragma unroll
            for (int jp = 0; jp < 4; jp++) {
                float v0, v1, v2, v3;
                unpack2(acc[jp][0], v0, v1);
                unpack2(acc[jp][1], v2, v3);
                *(float4*)(h1p + jp * 256 + p0 * 4) =
                    make_float4(fmaxf(v0, 0.f), fmaxf(v1, 0.f), fmaxf(v2, 0.f), fmaxf(v3, 0.f));
                unpack2(acc[jp][2], v0, v1);
                unpack2(acc[jp][3], v2, v3);
                *(float4*)(h1p + jp * 256 + p1 * 4) =
                    make_float4(fmaxf(v0, 0.f), fmaxf(v1, 0.f), fmaxf(v2, 0.f), fmaxf(v3, 0.f));
            }
        }
        __syncwarp();
        // ---- layer 2: 128 -> 64, lane owns o = 2lane, 2lane+1 ----
        {
            unsigned long long acc[4][2];
#pragma unroll
            for (int jp = 0; jp < 4; jp++) {
                acc[jp][0] = packdup(bb2_0);
                acc[jp][1] = packdup(bb2_1);
            }
#pragma unroll
            for (int c4 = 0; c4 < 32; c4++) {
                float4 WA = w2q[(2 * c4) * 32 + lane];
                float4 WB = w2q[(2 * c4 + 1) * 32 + lane];
                unsigned long long wd[4][2];
                wd[0][0] = packdup(WA.x); wd[0][1] = packdup(WA.y);
                wd[1][0] = packdup(WA.z); wd[1][1] = packdup(WA.w);
                wd[2][0] = packdup(WB.x); wd[2][1] = packdup(WB.y);
                wd[3][0] = packdup(WB.z); wd[3][1] = packdup(WB.w);
                int ua = 2 * c4, ub = 2 * c4 + 1;
                int pa = ua ^ ((ua >> 3) & 7);
                int pb = ub ^ ((ub >> 3) & 7);
#pragma unroll
                for (int jp = 0; jp < 4; jp++) {
                    ulonglong2 XA = *(const ulonglong2*)(h1p + jp * 256 + pa * 4);
                    ulonglong2 XB = *(const ulonglong2*)(h1p + jp * 256 + pb * 4);
                    fma2(acc[jp][0], wd[0][0], XA.x); fma2(acc[jp][1], wd[0][1], XA.x);
                    fma2(acc[jp][0], wd[1][0], XA.y); fma2(acc[jp][1], wd[1][1], XA.y);
                    fma2(acc[jp][0], wd[2][0], XB.x); fma2(acc[jp][1], wd[2][1], XB.x);
                    fma2(acc[jp][0], wd[3][0], XB.y); fma2(acc[jp][1], wd[3][1], XB.y);
                }
            }
#pragma unroll
            for (int jp = 0; jp < 4; jp++) {
                float v0, v1, v2, v3;
                unpack2(acc[jp][0], v0, v1);
                unpack2(acc[jp][1], v2, v3);
                *(float4*)(h2p + jp * 128 + 4 * lane) =
                    make_float4(fmaxf(v0, 0.f), fmaxf(v1, 0.f), fmaxf(v2, 0.f), fmaxf(v3, 0.f));
            }
        }
        __syncwarp();
        // ---- layer 3: 64 -> 64 + streaming aggregate with point flush ----
        {
            unsigned long long acc[4][2];
#pragma unroll
            for (int jp = 0; jp < 4; jp++) {
                acc[jp][0] = packdup(bb3_0);
                acc[jp][1] = packdup(bb3_1);
            }
#pragma unroll
            for (int c4 = 0; c4 < 16; c4++) {
                float4 WA = w3q[(2 * c4) * 32 + lane];
                float4 WB = w3q[(2 * c4 + 1) * 32 + lane];
                unsigned long long wd[4][2];
                wd[0][0] = packdup(WA.x); wd[0][1] = packdup(WA.y);
                wd[1][0] = packdup(WA.z); wd[1][1] = packdup(WA.w);
                wd[2][0] = packdup(WB.x); wd[2][1] = packdup(WB.y);
                wd[3][0] = packdup(WB.z); wd[3][1] = packdup(WB.w);
#pragma unroll
                for (int jp = 0; jp < 4; jp++) {
                    ulonglong2 XA = *(const ulonglong2*)(h2p + jp * 128 + 8 * c4);
                    ulonglong2 XB = *(const ulonglong2*)(h2p + jp * 128 + 8 * c4 + 4);
                    fma2(acc[jp][0], wd[0][0], XA.x); fma2(acc[jp][1], wd[0][1], XA.x);
                    fma2(acc[jp][0], wd[1][0], XA.y); fma2(acc[jp][1], wd[1][1], XA.y);
                    fma2(acc[jp][0], wd[2][0], XB.x); fma2(acc[jp][1], wd[2][1], XB.x);
                    fma2(acc[jp][0], wd[3][0], XB.y); fma2(acc[jp][1], wd[3][1], XB.y);
                }
            }
#pragma unroll
            for (int jp = 0; jp < 4; jp++) {
                float v00, v01, v10, v11;
                unpack2(acc[jp][0], v00, v01);
                unpack2(acc[jp][1], v10, v11);
#pragma unroll
                for (int h = 0; h < 2; h++) {
                    int col = 2 * jp + h;
                    float va = h ? v01 : v00;
                    float vb = h ? v11 : v10;
                    if (smnp[col]) {
                        if (open_i >= 0) {
                            int fb = open_i >> 12, fn = open_i & 4095;
                            out[((size_t)(fb * 64 + 2 * lane + 0)) * 4096 + fn] = agg0;
                            out[((size_t)(fb * 64 + 2 * lane + 1)) * 4096 + fn] = agg1;
                        }
                        open_i = smi[col];
                        agg0 = 0.f; agg1 = 0.f;
                    }
                    float w = smw[col];
                    agg0 = fmaf(w, fmaxf(va, 0.f), agg0);
                    agg1 = fmaf(w, fmaxf(vb, 0.f), agg1);
                }
            }
        }
        __syncwarp();
    }

    // flush the last open point
    if (open_i >= 0) {
        int fb = open_i >> 12, fn = open_i & 4095;
        out[((size_t)(fb * 64 + 2 * lane + 0)) * 4096 + fn] = agg0;
        out[((size_t)(fb * 64 + 2 * lane + 1)) * 4096 + fn] = agg1;
    }

    // ---- folded loss reduction (depends only on dist results) ----
    if (blockIdx.x == 0 && tid < 32) {
        float s = 0.f;
        for (int t2 = tid; t2 < 256; t2 += 32) s += g_rowpart[t2] + g_colpart[t2];
#pragma unroll
        for (int off = 16; off > 0; off >>= 1) s += __shfl_xor_sync(0xffffffffu, s, off);
        if (tid == 0) out[Bsz * 64 * Npts] = s * (1.0f / 8192.0f);
    }
}

extern "C" void kernel_launch(void* const* d_in, const int* in_sizes, int n_in,
                              void* d_out, int out_size) {
    const float* points    = (const float*)d_in[0];
    const float* knnpoints = (const float*)d_in[1];
    const float* feat      = (const float*)d_in[2];
    const float* w1 = (const float*)d_in[3];
    const float* b1 = (const float*)d_in[4];
    const float* w2 = (const float*)d_in[5];
    const float* b2 = (const float*)d_in[6];
    const float* w3 = (const float*)d_in[7];
    const float* b3 = (const float*)d_in[8];
    float* out = (float*)d_out;

    cudaFuncSetAttribute(distf_kernel, cudaFuncAttributeMaxDynamicSharedMemorySize, DIST_SMEM);
    cudaFuncSetAttribute(mlp_kernel,   cudaFuncAttributeMaxDynamicSharedMemorySize, SMEM_FLOATS * 4);

    int nsm = 148;
    cudaDeviceGetAttribute(&nsm, cudaDevAttrMultiProcessorCount, 0);

    distf_kernel<<<640, 256, DIST_SMEM>>>(points, knnpoints, feat, w1, b1);
    mlp_kernel<<<nsm, NTHR, SMEM_FLOATS * 4>>>(points, knnpoints, w1, w2, b2, w3, b3, out);
}